// round 14
// baseline (speedup 1.0000x reference)
#include <cuda_runtime.h>
#include <cuda_bf16.h>
#include <math.h>
#include <stdint.h>

#define NNODES 100000
#define NEDGES 3200000
#define NFEAT  512
#define NH     256
#define NC     40
#define NL     8
#define ALPHA  0.1f

// ---------------- scratch (device globals; no allocation allowed) ----------------
__device__ __align__(16) float g_h  [(size_t)NNODES * NH];
__device__ __align__(16) float g_h0 [(size_t)NNODES * NH];
__device__ __align__(16) __nv_bfloat16 g_hbA[(size_t)NNODES * NH];   // ping
__device__ __align__(16) __nv_bfloat16 g_hbB[(size_t)NNODES * NH];   // pong
__device__ __align__(16) float g_wtf[(size_t)NH * NFEAT + (size_t)NL * NH * NH];
__device__ __align__(16) int2 g_edge[NEDGES];
__device__ int   g_rowptr[NNODES + 1];
__device__ int   g_cursor[NNODES];
__device__ int   g_partial[1024];

__device__ __forceinline__ uint32_t smem_u32(const void* p) {
    uint32_t a;
    asm("{ .reg .u64 t; cvta.to.shared.u64 t, %1; cvt.u32.u64 %0, t; }" : "=r"(a) : "l"(p));
    return a;
}
__device__ __forceinline__ uint32_t tf32_u(float x) {
    uint32_t u;
    asm("cvt.rna.tf32.f32 %0, %1;" : "=r"(u) : "f"(x));
    return u;
}
__device__ __forceinline__ float tf32_f(float x) { return __uint_as_float(tf32_u(x)); }

__device__ __forceinline__ void cp16(uint32_t dst, const void* src, int bytes) {
    asm volatile("cp.async.ca.shared.global [%0], [%1], 16, %2;"
                 :: "r"(dst), "l"(src), "r"(bytes) : "memory");
}
#define CP_COMMIT() asm volatile("cp.async.commit_group;" ::: "memory")
#define CP_WAIT1()  asm volatile("cp.async.wait_group 1;" ::: "memory")
#define CP_WAIT0()  asm volatile("cp.async.wait_group 0;" ::: "memory")

#define LDSM4(r0, r1, r2, r3, addr)                                              \
    asm volatile("ldmatrix.sync.aligned.m8n8.x4.shared.b16 {%0,%1,%2,%3}, [%4];" \
                 : "=r"(r0), "=r"(r1), "=r"(r2), "=r"(r3) : "r"(addr))

// ---------------- CSR construction ----------------
__global__ void k_zero_counts(int n) {
    for (int i = blockIdx.x * blockDim.x + threadIdx.x; i < n; i += gridDim.x * blockDim.x)
        g_rowptr[i] = 0;
}
__global__ void k_hist(const int* __restrict__ rows, int e) {
    for (int i = blockIdx.x * blockDim.x + threadIdx.x; i < e; i += gridDim.x * blockDim.x)
        atomicAdd(&g_rowptr[rows[i] + 1], 1);
}
__global__ void k_scan_block(int n) {
    __shared__ int s[1024];
    int i = blockIdx.x * 1024 + threadIdx.x;
    int v = (i < n) ? g_rowptr[i] : 0;
    s[threadIdx.x] = v;
    __syncthreads();
    #pragma unroll
    for (int off = 1; off < 1024; off <<= 1) {
        int t = (threadIdx.x >= off) ? s[threadIdx.x - off] : 0;
        __syncthreads();
        s[threadIdx.x] += t;
        __syncthreads();
    }
    if (i < n) g_rowptr[i] = s[threadIdx.x];
    if (threadIdx.x == 1023) g_partial[blockIdx.x] = s[1023];
}
__global__ void k_scan_partials(int nb) {
    __shared__ int s[1024];
    int v = (threadIdx.x < nb) ? g_partial[threadIdx.x] : 0;
    s[threadIdx.x] = v;
    __syncthreads();
    #pragma unroll
    for (int off = 1; off < 1024; off <<= 1) {
        int t = (threadIdx.x >= off) ? s[threadIdx.x - off] : 0;
        __syncthreads();
        s[threadIdx.x] += t;
        __syncthreads();
    }
    if (threadIdx.x < nb) g_partial[threadIdx.x] = s[threadIdx.x];
}
__global__ void k_scan_add_cursor(int n) {
    int i = blockIdx.x * 1024 + threadIdx.x;
    if (i < n) {
        int v = g_rowptr[i];
        if (blockIdx.x > 0) { v += g_partial[blockIdx.x - 1]; g_rowptr[i] = v; }
        if (i < n - 1) g_cursor[i] = v;
    }
}
__global__ void k_scatter(const int* __restrict__ rows, const int* __restrict__ cols,
                          const float* __restrict__ vals, int e) {
    for (int i = blockIdx.x * blockDim.x + threadIdx.x; i < e; i += gridDim.x * blockDim.x) {
        int r = rows[i];
        int p = atomicAdd(&g_cursor[r], 1);
        g_edge[p] = make_int2(cols[i], __float_as_int(vals[i]));
    }
}

// ---------------- weight transpose + tf32 round: WT[n][k] = rna(W[k][n]) ----------------
__global__ void k_wtrans(const float* __restrict__ W, float* __restrict__ WT,
                         int K, int N) {
    __shared__ float tb[32][33];
    int k0 = blockIdx.x * 32, n0 = blockIdx.y * 32;
    int x = threadIdx.x, y = threadIdx.y;
    #pragma unroll
    for (int i = 0; i < 32; i += 8)
        tb[y + i][x] = W[(size_t)(k0 + y + i) * N + n0 + x];
    __syncthreads();
    #pragma unroll
    for (int i = 0; i < 32; i += 8)
        WT[(size_t)(n0 + y + i) * K + k0 + x] = tf32_f(tb[x][y + i]);
}
__global__ void k_wtrans_l(const float* __restrict__ W, float* __restrict__ WT) {
    __shared__ float tb[32][33];
    int l = blockIdx.z;
    int k0 = blockIdx.x * 32, n0 = blockIdx.y * 32;
    int x = threadIdx.x, y = threadIdx.y;
    const float* Wl = W + (size_t)l * NH * NH;
    float* WTl = WT + (size_t)l * NH * NH;
    #pragma unroll
    for (int i = 0; i < 32; i += 8)
        tb[y + i][x] = Wl[(size_t)(k0 + y + i) * NH + n0 + x];
    __syncthreads();
    #pragma unroll
    for (int i = 0; i < 32; i += 8)
        WTl[(size_t)(n0 + y + i) * NH + k0 + x] = tf32_f(tb[x][y + i]);
}

// ---------------- bf16 gather helpers ----------------
__device__ __forceinline__ void bf2_fma(uint32_t w, float v, float& a0, float& a1) {
    a0 += v * __uint_as_float(w << 16);
    a1 += v * __uint_as_float(w & 0xFFFF0000u);
}
__device__ __forceinline__ void acc_edge(uint4 x, float v, float* acc) {
    bf2_fma(x.x, v, acc[0], acc[1]); bf2_fma(x.y, v, acc[2], acc[3]);
    bf2_fma(x.z, v, acc[4], acc[5]); bf2_fma(x.w, v, acc[6], acc[7]);
}

__device__ __forceinline__ void mma_tf32(float& c0, float& c1, float& c2, float& c3,
                                         uint32_t a0, uint32_t a1, uint32_t a2, uint32_t a3,
                                         uint32_t b0, uint32_t b1) {
    asm volatile(
        "mma.sync.aligned.m16n8k8.row.col.f32.tf32.tf32.f32 "
        "{%0,%1,%2,%3}, {%4,%5,%6,%7}, {%8,%9}, {%0,%1,%2,%3};"
        : "+f"(c0), "+f"(c1), "+f"(c2), "+f"(c3)
        : "r"(a0), "r"(a1), "r"(a2), "r"(a3), "r"(b0), "r"(b1));
}

// ================= FUSED layer kernel: SpMM -> smem -> GEMM =================
// Block: 128 rows x all 256 cols. 512 threads, 16 warps (2m x 8n), warp tile 64x32.
// Phase 1: support = tf32(0.9*(G@hb_in) + 0.1*h0) into smem A-tile [128][FA_STR].
// Phase 2: D = A @ WT^T (K=256, 8 chunks of 32, B double-buffered cp.async).
// Epilogue: o = relu(th*D + (1-th)*A_smem); Cb = bf16 OUT buffer (ping-pong, != hb_in).
#define FA_STR 260
#define FB_STR 36
#define FA_EL  (128 * FA_STR)
#define FB_EL  (256 * FB_STR)
#define FU_SMEM ((FA_EL + 2 * FB_EL) * 4)     // 206848 bytes

__global__ void __launch_bounds__(512, 1)
k_fused(const __nv_bfloat16* __restrict__ hb, const float* __restrict__ h0,
        const float* __restrict__ WT, float th,
        float* __restrict__ Cf, __nv_bfloat16* __restrict__ Cb, int M) {
    extern __shared__ float sm[];
    float* smA = sm;                          // [128][FA_STR]
    float* smB = sm + FA_EL;                  // [2][256][FB_STR]
    uint32_t sA = smem_u32(smA);
    uint32_t sB = smem_u32(smB);

    int tid  = threadIdx.x;
    int lane = tid & 31;
    int m0   = blockIdx.x * 128;

    // ---- B staging coords: 256 rows, 2 threads/row, 16 floats each ----
    int brow = tid >> 1, bhalf = (tid & 1) << 4;
    const float* Bsrc = WT + (size_t)brow * NH + bhalf;
    uint32_t dB0 = sB + (brow * FB_STR + bhalf) * 4;

    // prefetch B chunk 0 (independent of phase 1)
    {
        #pragma unroll
        for (int q = 0; q < 4; ++q) cp16(dB0 + q * 16, Bsrc + q * 4, 16);
        CP_COMMIT();
    }

    // ---- Phase 1: SpMM + residual into smem A ----
    {
        int wq = tid >> 5;                    // warp 0..15
        const uint4* __restrict__ hb4 = (const uint4*)hb;
        const float4* __restrict__ h04 = (const float4*)h0;
        for (int rr = 0; rr < 8; ++rr) {
            int rl = wq * 8 + rr;
            int row = m0 + rl;
            float acc[8] = {0.f, 0.f, 0.f, 0.f, 0.f, 0.f, 0.f, 0.f};
            float4 oA = make_float4(0.f, 0.f, 0.f, 0.f);
            float4 oB = make_float4(0.f, 0.f, 0.f, 0.f);
            if (row < M) {
                int beg = g_rowptr[row], end = g_rowptr[row + 1];
                int e = beg;
                for (; e + 4 <= end; e += 4) {
                    int2 E0 = g_edge[e],     E1 = g_edge[e + 1];
                    int2 E2 = g_edge[e + 2], E3 = g_edge[e + 3];
                    uint4 x0 = hb4[E0.x * 32 + lane];
                    uint4 x1 = hb4[E1.x * 32 + lane];
                    uint4 x2 = hb4[E2.x * 32 + lane];
                    uint4 x3 = hb4[E3.x * 32 + lane];
                    acc_edge(x0, __int_as_float(E0.y), acc);
                    acc_edge(x1, __int_as_float(E1.y), acc);
                    acc_edge(x2, __int_as_float(E2.y), acc);
                    acc_edge(x3, __int_as_float(E3.y), acc);
                }
                for (; e < end; ++e) {
                    int2 E = g_edge[e];
                    uint4 x = hb4[E.x * 32 + lane];
                    acc_edge(x, __int_as_float(E.y), acc);
                }
                float4 z0 = h04[(size_t)row * 64 + lane * 2];
                float4 z1 = h04[(size_t)row * 64 + lane * 2 + 1];
                oA.x = tf32_f((1.f - ALPHA) * acc[0] + ALPHA * z0.x);
                oA.y = tf32_f((1.f - ALPHA) * acc[1] + ALPHA * z0.y);
                oA.z = tf32_f((1.f - ALPHA) * acc[2] + ALPHA * z0.z);
                oA.w = tf32_f((1.f - ALPHA) * acc[3] + ALPHA * z0.w);
                oB.x = tf32_f((1.f - ALPHA) * acc[4] + ALPHA * z1.x);
                oB.y = tf32_f((1.f - ALPHA) * acc[5] + ALPHA * z1.y);
                oB.z = tf32_f((1.f - ALPHA) * acc[6] + ALPHA * z1.z);
                oB.w = tf32_f((1.f - ALPHA) * acc[7] + ALPHA * z1.w);
            }
            *reinterpret_cast<float4*>(&smA[rl * FA_STR + lane * 8])     = oA;
            *reinterpret_cast<float4*>(&smA[rl * FA_STR + lane * 8 + 4]) = oB;
        }
    }
    __syncthreads();

    // ---- Phase 2: GEMM ----
    int wid = tid >> 5;
    int g   = lane >> 2, t = lane & 3;
    int wm  = wid & 1;                        // 2 warps in M (64 rows)
    int wn  = wid >> 1;                       // 8 warps in N (32 cols)
    int lr  = lane & 7, sel = lane >> 3;
    uint32_t a_base = sA + (uint32_t)(((wm * 64 + lr + (sel & 1) * 8) * FA_STR + (sel >> 1) * 4) * 4);
    uint32_t b_base = sB + (uint32_t)(((wn * 32 + (sel >> 1) * 8 + lr) * FB_STR + (sel & 1) * 4) * 4);

    float c[4][4][4];
    #pragma unroll
    for (int i = 0; i < 4; ++i)
        #pragma unroll
        for (int j = 0; j < 4; ++j)
            #pragma unroll
            for (int q = 0; q < 4; ++q) c[i][j][q] = 0.f;

    for (int ch = 0; ch < 8; ++ch) {
        int buf = ch & 1;
        if (ch < 7) {
            int k0 = (ch + 1) << 5;
            uint32_t dB = dB0 + (buf ^ 1) * FB_EL * 4;
            const float* src = Bsrc + k0;
            #pragma unroll
            for (int q = 0; q < 4; ++q) cp16(dB + q * 16, src + q * 4, 16);
            CP_COMMIT();
            CP_WAIT1();
        } else {
            CP_WAIT0();
        }
        __syncthreads();

        uint32_t bb = b_base + buf * FB_EL * 4;
        #pragma unroll
        for (int ks = 0; ks < 4; ++ks) {
            uint32_t koffA = (uint32_t)((ch * 32 + ks * 8) * 4);
            uint32_t koffB = (uint32_t)(ks * 8 * 4);
            uint32_t af[4][4];
            #pragma unroll
            for (int mf = 0; mf < 4; ++mf)
                LDSM4(af[mf][0], af[mf][1], af[mf][2], af[mf][3],
                      a_base + (uint32_t)(mf * 16 * FA_STR * 4) + koffA);
            uint32_t bf[4][2];
            #pragma unroll
            for (int p = 0; p < 2; ++p)
                LDSM4(bf[2 * p][0], bf[2 * p][1], bf[2 * p + 1][0], bf[2 * p + 1][1],
                      bb + (uint32_t)(p * 16 * FB_STR * 4) + koffB);
            #pragma unroll
            for (int mf = 0; mf < 4; ++mf)
                #pragma unroll
                for (int nf = 0; nf < 4; ++nf)
                    mma_tf32(c[mf][nf][0], c[mf][nf][1], c[mf][nf][2], c[mf][nf][3],
                             af[mf][0], af[mf][1], af[mf][2], af[mf][3],
                             bf[nf][0], bf[nf][1]);
        }
        __syncthreads();
    }

    // ---- epilogue: o = relu(th*D + (1-th)*R), R from smem A ----
    float oth = 1.f - th;
    #pragma unroll
    for (int mf = 0; mf < 4; ++mf) {
        int rl0 = wm * 64 + mf * 16 + g;
        #pragma unroll
        for (int nf = 0; nf < 4; ++nf) {
            int ncol = wn * 32 + nf * 8 + 2 * t;
            #pragma unroll
            for (int half = 0; half < 2; ++half) {
                int rl = rl0 + half * 8;
                int m = m0 + rl;
                if (m >= M) continue;
                float d0 = c[mf][nf][half * 2 + 0];
                float d1 = c[mf][nf][half * 2 + 1];
                float2 r2 = *reinterpret_cast<const float2*>(&smA[rl * FA_STR + ncol]);
                float2 o = make_float2(fmaxf(th * d0 + oth * r2.x, 0.f),
                                       fmaxf(th * d1 + oth * r2.y, 0.f));
                if (Cf)
                    *reinterpret_cast<float2*>(Cf + (size_t)m * NH + ncol) = o;
                if (Cb)
                    *reinterpret_cast<__nv_bfloat162*>(Cb + (size_t)m * NH + ncol) =
                        __float22bfloat162_rn(o);
            }
        }
    }
}

// ---------------- tf32 GEMM (input layer): R10 config ----------------
#define ASTR 36
#define TILE_EL (128 * ASTR)
#define MG_SMEM (4 * TILE_EL * 4)

__global__ void __launch_bounds__(256, 2)
k_mgemm(const float* __restrict__ A, const float* __restrict__ WT,
        const float* __restrict__ bias,
        float* __restrict__ C2, __nv_bfloat16* __restrict__ Cb,
        int M, int K) {
    extern __shared__ float sm[];
    float* smA = sm;
    float* smB = sm + 2 * TILE_EL;
    uint32_t sA = smem_u32(smA);
    uint32_t sB = smem_u32(smB);

    int tid  = threadIdx.x;
    int wid  = tid >> 5, lane = tid & 31;
    int g    = lane >> 2, t = lane & 3;
    int wm   = wid & 1;
    int wn   = wid >> 1;
    int m0   = blockIdx.x * 128;
    int n0   = blockIdx.y * 128;
    int nc   = K >> 5;

    int lr = lane & 7, sel = lane >> 3;
    uint32_t a_base = (uint32_t)(((wm * 64 + lr + (sel & 1) * 8) * ASTR + (sel >> 1) * 4) * 4);
    uint32_t b_base = (uint32_t)(((wn * 32 + (sel >> 1) * 8 + lr) * ASTR + (sel & 1) * 4) * 4);

    int sr = tid >> 1, scol = (tid & 1) << 4;
    const float* Asrc = A  + (size_t)(m0 + sr) * K + scol;
    const float* Bsrc = WT + (size_t)(n0 + sr) * K + scol;
    int abytes = (m0 + sr < M) ? 16 : 0;
    uint32_t dA0 = sA + (sr * ASTR + scol) * 4;
    uint32_t dB0 = sB + (sr * ASTR + scol) * 4;

    {
        #pragma unroll
        for (int q = 0; q < 4; ++q) cp16(dA0 + q * 16, Asrc + q * 4, abytes);
        #pragma unroll
        for (int q = 0; q < 4; ++q) cp16(dB0 + q * 16, Bsrc + q * 4, 16);
        CP_COMMIT();
    }

    float c[4][4][4];
    #pragma unroll
    for (int i = 0; i < 4; ++i)
        #pragma unroll
        for (int j = 0; j < 4; ++j)
            #pragma unroll
            for (int q = 0; q < 4; ++q) c[i][j][q] = 0.f;

    for (int ch = 0; ch < nc; ++ch) {
        int buf = ch & 1;
        bool more = (ch + 1 < nc);
        if (more) {
            int k0 = (ch + 1) << 5;
            int bo = buf ^ 1;
            uint32_t dA = dA0 + bo * TILE_EL * 4;
            uint32_t dB = dB0 + bo * TILE_EL * 4;
            #pragma unroll
            for (int q = 0; q < 4; ++q) cp16(dA + q * 16, Asrc + k0 + q * 4, abytes);
            #pragma unroll
            for (int q = 0; q < 4; ++q) cp16(dB + q * 16, Bsrc + k0 + q * 4, 16);
            CP_COMMIT();
            CP_WAIT1();
        } else {
            CP_WAIT0();
        }
        __syncthreads();

        uint32_t ab = sA + buf * TILE_EL * 4 + a_base;
        uint32_t bb = sB + buf * TILE_EL * 4 + b_base;
        #pragma unroll
        for (int ks = 0; ks < 4; ++ks) {
            uint32_t koff = (uint32_t)(ks * 8 * 4);
            uint32_t af[4][4];
            #pragma unroll
            for (int mf = 0; mf < 4; ++mf)
                LDSM4(af[mf][0], af[mf][1], af[mf][2], af[mf][3],
                      ab + (uint32_t)(mf * 16 * ASTR * 4) + koff);
            uint32_t bf[4][2];
            #pragma unroll
            for (int p = 0; p < 2; ++p)
                LDSM4(bf[2 * p][0], bf[2 * p][1], bf[2 * p + 1][0], bf[2 * p + 1][1],
                      bb + (uint32_t)(p * 16 * ASTR * 4) + koff);
            #pragma unroll
            for (int mf = 0; mf < 4; ++mf)
                #pragma unroll
                for (int q = 0; q < 4; ++q)
                    af[mf][q] = tf32_u(__uint_as_float(af[mf][q]));
            #pragma unroll
            for (int mf = 0; mf < 4; ++mf)
                #pragma unroll
                for (int nf = 0; nf < 4; ++nf)
                    mma_tf32(c[mf][nf][0], c[mf][nf][1], c[mf][nf][2], c[mf][nf][3],
                             af[mf][0], af[mf][1], af[mf][2], af[mf][3],
                             bf[nf][0], bf[nf][1]);
        }
        __syncthreads();
    }

    #pragma unroll
    for (int mf = 0; mf < 4; ++mf) {
        int r0 = m0 + wm * 64 + mf * 16 + g;
        #pragma unroll
        for (int nf = 0; nf < 4; ++nf) {
            int ncol = n0 + wn * 32 + nf * 8 + 2 * t;
            #pragma unroll
            for (int half = 0; half < 2; ++half) {
                int m = r0 + half * 8;
                if (m >= M) continue;
                float d0 = c[mf][nf][half * 2 + 0];
                float d1 = c[mf][nf][half * 2 + 1];
                float2 o = make_float2(fmaxf(d0 + bias[ncol], 0.f),
                                       fmaxf(d1 + bias[ncol + 1], 0.f));
                *reinterpret_cast<float2*>(C2 + (size_t)m * NH + ncol) = o;
                *reinterpret_cast<__nv_bfloat162*>(Cb + (size_t)m * NH + ncol) =
                    __float22bfloat162_rn(o);
            }
        }
    }
}

// ---------------- narrow tf32 GEMM (output layer, N=40) ----------------
#define KC 32
#define NSTRIDE 136
#define NA_EL (128 * ASTR)
#define NB_EL (KC * NSTRIDE)
#define N_SMEM ((2 * NA_EL + 2 * NB_EL) * 4)

__global__ void __launch_bounds__(256, 2)
k_ngemm(const float* __restrict__ A, const float* __restrict__ B,
        const float* __restrict__ bias, float* __restrict__ C,
        int M, int K, int Nn) {
    extern __shared__ float sm[];
    float* smA = sm;
    float* smB = sm + 2 * NA_EL;
    uint32_t sA = smem_u32(smA);
    uint32_t sB = smem_u32(smB);

    int tid  = threadIdx.x;
    int wid  = tid >> 5, lane = tid & 31;
    int g    = lane >> 2, t = lane & 3;
    int wm   = wid & 1;
    int wn   = wid >> 1;
    int m0   = blockIdx.x * 128;
    int nc   = K / KC;

    int ar = tid >> 1, ac = (tid & 1) << 4;
    int br = tid >> 3, bc = (tid & 7) << 4;

    const float* Asrc = A + (size_t)(m0 + ar) * K + ac;
    int abytes = (m0 + ar < M) ? 16 : 0;

    {
        cp16(sA + (ar * ASTR + ac) * 4, Asrc, abytes);
        cp16(sA + (ar * ASTR + ac + 4) * 4, Asrc + 4, abytes);
        cp16(sA + (ar * ASTR + ac + 8) * 4, Asrc + 8, abytes);
        cp16(sA + (ar * ASTR + ac + 12) * 4, Asrc + 12, abytes);
        #pragma unroll
        for (int q = 0; q < 4; ++q) {
            int gn = bc + q * 4;
            int bbytes = (Nn - gn >= 4) ? 16 : ((Nn - gn > 0) ? (Nn - gn) * 4 : 0);
            cp16(sB + (br * NSTRIDE + bc + q * 4) * 4,
                 B + (size_t)br * Nn + ((bbytes > 0) ? gn : 0), bbytes);
        }
        CP_COMMIT();
    }

    float c[4][4][4];
    #pragma unroll
    for (int i = 0; i < 4; ++i)
        #pragma unroll
        for (int j = 0; j < 4; ++j)
            #pragma unroll
            for (int q = 0; q < 4; ++q) c[i][j][q] = 0.f;

    for (int ch = 0; ch < nc; ++ch) {
        int buf = ch & 1;
        bool more = (ch + 1 < nc);
        if (more) {
            int k0 = (ch + 1) * KC;
            int bo = (buf ^ 1);
            uint32_t dA = sA + (bo * NA_EL + ar * ASTR + ac) * 4;
            const float* src = Asrc + k0;
            cp16(dA,      src,      abytes);
            cp16(dA + 16, src + 4,  abytes);
            cp16(dA + 32, src + 8,  abytes);
            cp16(dA + 48, src + 12, abytes);
            #pragma unroll
            for (int q = 0; q < 4; ++q) {
                int gn = bc + q * 4;
                int bbytes = (Nn - gn >= 4) ? 16 : ((Nn - gn > 0) ? (Nn - gn) * 4 : 0);
                cp16(sB + (bo * NB_EL + br * NSTRIDE + bc + q * 4) * 4,
                     B + (size_t)(k0 + br) * Nn + ((bbytes > 0) ? gn : 0), bbytes);
            }
            CP_COMMIT();
            CP_WAIT1();
        } else {
            CP_WAIT0();
        }
        __syncthreads();

        const float* As = smA + buf * NA_EL;
        const float* Bs = smB + buf * NB_EL;
        #pragma unroll
        for (int ks = 0; ks < 4; ++ks) {
            int kk = ks * 8;
            uint32_t af[4][4];
            #pragma unroll
            for (int mf = 0; mf < 4; ++mf) {
                int r = wm * 64 + mf * 16 + g;
                af[mf][0] = tf32_u(As[(r    ) * ASTR + kk + t    ]);
                af[mf][1] = tf32_u(As[(r + 8) * ASTR + kk + t    ]);
                af[mf][2] = tf32_u(As[(r    ) * ASTR + kk + t + 4]);
                af[mf][3] = tf32_u(As[(r + 8) * ASTR + kk + t + 4]);
            }
            uint32_t bf[4][2];
            #pragma unroll
            for (int nf = 0; nf < 4; ++nf) {
                int ncol = wn * 32 + nf * 8 + g;
                bf[nf][0] = tf32_u(Bs[(kk + t    ) * NSTRIDE + ncol]);
                bf[nf][1] = tf32_u(Bs[(kk + t + 4) * NSTRIDE + ncol]);
            }
            #pragma unroll
            for (int mf = 0; mf < 4; ++mf)
                #pragma unroll
                for (int nf = 0; nf < 4; ++nf)
                    mma_tf32(c[mf][nf][0], c[mf][nf][1], c[mf][nf][2], c[mf][nf][3],
                             af[mf][0], af[mf][1], af[mf][2], af[mf][3],
                             bf[nf][0], bf[nf][1]);
        }
        __syncthreads();
    }

    #pragma unroll
    for (int mf = 0; mf < 4; ++mf) {
        int r0 = m0 + wm * 64 + mf * 16 + g;
        #pragma unroll
        for (int nf = 0; nf < 4; ++nf) {
            int ncol = wn * 32 + nf * 8 + 2 * t;
            #pragma unroll
            for (int half = 0; half < 2; ++half) {
                int m = r0 + half * 8;
                if (m >= M) continue;
                float d0 = c[mf][nf][half * 2 + 0];
                float d1 = c[mf][nf][half * 2 + 1];
                if (ncol < Nn)     C[(size_t)m * Nn + ncol]     = d0 + bias[ncol];
                if (ncol + 1 < Nn) C[(size_t)m * Nn + ncol + 1] = d1 + bias[ncol + 1];
            }
        }
    }
}

// ---------------- launch ----------------
extern "C" void kernel_launch(void* const* d_in, const int* in_sizes, int n_in,
                              void* d_out, int out_size) {
    const float* features = (const float*)d_in[0];
    const int*   erows    = (const int*)  d_in[1];
    const int*   ecols    = (const int*)  d_in[2];
    const float* evals    = (const float*)d_in[3];
    const float* W_in     = (const float*)d_in[4];
    const float* b_in     = (const float*)d_in[5];
    const float* convW    = (const float*)d_in[6];
    const float* W_out    = (const float*)d_in[7];
    const float* b_out    = (const float*)d_in[8];
    float* out = (float*)d_out;

    const int E = in_sizes[1];
    const int Mn = NNODES;

    float* d_h;   cudaGetSymbolAddress((void**)&d_h,   g_h);
    float* d_h0;  cudaGetSymbolAddress((void**)&d_h0,  g_h0);
    float* d_wtf; cudaGetSymbolAddress((void**)&d_wtf, g_wtf);
    __nv_bfloat16* d_hbA; cudaGetSymbolAddress((void**)&d_hbA, g_hbA);
    __nv_bfloat16* d_hbB; cudaGetSymbolAddress((void**)&d_hbB, g_hbB);

    cudaFuncSetAttribute(k_mgemm, cudaFuncAttributeMaxDynamicSharedMemorySize, MG_SMEM);
    cudaFuncSetAttribute(k_ngemm, cudaFuncAttributeMaxDynamicSharedMemorySize, N_SMEM);
    cudaFuncSetAttribute(k_fused, cudaFuncAttributeMaxDynamicSharedMemorySize, FU_SMEM);

    float* d_wt_in = d_wtf;                              // [256][512]
    float* d_wt_l  = d_wtf + (size_t)NH * NFEAT;         // NL x [256][256]

    int mg = (Mn + 127) / 128;
    dim3 tblk(32, 8);
    int np1 = Mn + 1;
    int nscan_blocks = (np1 + 1023) / 1024;

    // launch order keeps the input GEMM at index 3 (ncu capture target)
    k_zero_counts<<<(np1 + 255) / 256, 256>>>(np1);                           // 0
    k_hist<<<(E + 255) / 256, 256>>>(erows, E);                               // 1
    k_wtrans<<<dim3(NFEAT / 32, NH / 32), tblk>>>(W_in, d_wt_in, NFEAT, NH);  // 2

    // input layer: h0 = relu(F @ W_in + b_in); hbA = bf16(h0)
    k_mgemm<<<dim3(mg, 2), 256, MG_SMEM>>>(features, d_wt_in, b_in,
                                           d_h0, d_hbA, Mn, NFEAT);           // 3

    k_scan_block<<<nscan_blocks, 1024>>>(np1);                                // 4
    k_scan_partials<<<1, 1024>>>(nscan_blocks);                               // 5
    k_scan_add_cursor<<<nscan_blocks, 1024>>>(np1);                           // 6
    k_scatter<<<(E + 255) / 256, 256>>>(erows, ecols, evals, E);              // 7
    k_wtrans_l<<<dim3(NH / 32, NH / 32, NL), tblk>>>(convW, d_wt_l);          // 8

    // ---- GCNII layers: fused SpMM + GEMM, ping-pong bf16 state ----
    __nv_bfloat16* hb_in  = d_hbA;
    __nv_bfloat16* hb_out = d_hbB;
    for (int l = 0; l < NL; ++l) {
        float theta = logf(0.5f / (float)(l + 1) + 1.0f);
        bool last = (l + 1 == NL);
        k_fused<<<mg, 512, FU_SMEM>>>(hb_in, d_h0, d_wt_l + (size_t)l * NH * NH,
                                      theta, last ? d_h : nullptr,
                                      last ? nullptr : hb_out, Mn);
        __nv_bfloat16* tswap = hb_in; hb_in = hb_out; hb_out = tswap;
    }

    // ---- output layer ----
    k_ngemm<<<dim3(mg, 1), 256, N_SMEM>>>(d_h, W_out, b_out, out, Mn, NH, NC);
}

// round 15
// speedup vs baseline: 1.5638x; 1.5638x over previous
#include <cuda_runtime.h>
#include <cuda_bf16.h>
#include <math.h>
#include <stdint.h>

#define NNODES 100000
#define NEDGES 3200000
#define NFEAT  512
#define NH     256
#define NC     40
#define NL     8
#define ALPHA  0.1f

// ---------------- scratch (device globals; no allocation allowed) ----------------
__device__ __align__(16) float g_h  [(size_t)NNODES * NH];
__device__ __align__(16) float g_h0 [(size_t)NNODES * NH];
__device__ __align__(16) float g_tmp[(size_t)NNODES * NH];
__device__ __align__(16) __nv_bfloat16 g_hb[(size_t)NNODES * NH];
__device__ __align__(16) float g_wtf[(size_t)NH * NFEAT + (size_t)NL * NH * NH];
__device__ __align__(16) int2 g_edge[NEDGES];
__device__ int   g_rowptr[NNODES + 1];
__device__ int   g_cursor[NNODES];
__device__ int   g_partial[1024];

__device__ __forceinline__ uint32_t smem_u32(const void* p) {
    uint32_t a;
    asm("{ .reg .u64 t; cvta.to.shared.u64 t, %1; cvt.u32.u64 %0, t; }" : "=r"(a) : "l"(p));
    return a;
}
__device__ __forceinline__ uint32_t tf32_u(float x) {
    uint32_t u;
    asm("cvt.rna.tf32.f32 %0, %1;" : "=r"(u) : "f"(x));
    return u;
}
__device__ __forceinline__ float tf32_f(float x) { return __uint_as_float(tf32_u(x)); }

__device__ __forceinline__ void cp16(uint32_t dst, const void* src, int bytes) {
    asm volatile("cp.async.ca.shared.global [%0], [%1], 16, %2;"
                 :: "r"(dst), "l"(src), "r"(bytes) : "memory");
}
#define CP_COMMIT() asm volatile("cp.async.commit_group;" ::: "memory")
#define CP_WAIT1()  asm volatile("cp.async.wait_group 1;" ::: "memory")
#define CP_WAIT0()  asm volatile("cp.async.wait_group 0;" ::: "memory")

#define LDSM4(r0, r1, r2, r3, addr)                                              \
    asm volatile("ldmatrix.sync.aligned.m8n8.x4.shared.b16 {%0,%1,%2,%3}, [%4];" \
                 : "=r"(r0), "=r"(r1), "=r"(r2), "=r"(r3) : "r"(addr))

// ---------------- CSR construction ----------------
__global__ void k_zero_counts(int n) {
    for (int i = blockIdx.x * blockDim.x + threadIdx.x; i < n; i += gridDim.x * blockDim.x)
        g_rowptr[i] = 0;
}
__global__ void k_hist(const int* __restrict__ rows, int e) {
    for (int i = blockIdx.x * blockDim.x + threadIdx.x; i < e; i += gridDim.x * blockDim.x)
        atomicAdd(&g_rowptr[rows[i] + 1], 1);
}
__global__ void k_scan_block(int n) {
    __shared__ int s[1024];
    int i = blockIdx.x * 1024 + threadIdx.x;
    int v = (i < n) ? g_rowptr[i] : 0;
    s[threadIdx.x] = v;
    __syncthreads();
    #pragma unroll
    for (int off = 1; off < 1024; off <<= 1) {
        int t = (threadIdx.x >= off) ? s[threadIdx.x - off] : 0;
        __syncthreads();
        s[threadIdx.x] += t;
        __syncthreads();
    }
    if (i < n) g_rowptr[i] = s[threadIdx.x];
    if (threadIdx.x == 1023) g_partial[blockIdx.x] = s[1023];
}
__global__ void k_scan_partials(int nb) {
    __shared__ int s[1024];
    int v = (threadIdx.x < nb) ? g_partial[threadIdx.x] : 0;
    s[threadIdx.x] = v;
    __syncthreads();
    #pragma unroll
    for (int off = 1; off < 1024; off <<= 1) {
        int t = (threadIdx.x >= off) ? s[threadIdx.x - off] : 0;
        __syncthreads();
        s[threadIdx.x] += t;
        __syncthreads();
    }
    if (threadIdx.x < nb) g_partial[threadIdx.x] = s[threadIdx.x];
}
__global__ void k_scan_add_cursor(int n) {
    int i = blockIdx.x * 1024 + threadIdx.x;
    if (i < n) {
        int v = g_rowptr[i];
        if (blockIdx.x > 0) { v += g_partial[blockIdx.x - 1]; g_rowptr[i] = v; }
        if (i < n - 1) g_cursor[i] = v;
    }
}
__global__ void k_scatter(const int* __restrict__ rows, const int* __restrict__ cols,
                          const float* __restrict__ vals, int e) {
    for (int i = blockIdx.x * blockDim.x + threadIdx.x; i < e; i += gridDim.x * blockDim.x) {
        int r = rows[i];
        int p = atomicAdd(&g_cursor[r], 1);
        g_edge[p] = make_int2(cols[i], __float_as_int(vals[i]));
    }
}

// ---------------- weight transpose + tf32 round: WT[n][k] = rna(W[k][n]) ----------------
__global__ void k_wtrans(const float* __restrict__ W, float* __restrict__ WT,
                         int K, int N) {
    __shared__ float tb[32][33];
    int k0 = blockIdx.x * 32, n0 = blockIdx.y * 32;
    int x = threadIdx.x, y = threadIdx.y;   // 32 x 8
    #pragma unroll
    for (int i = 0; i < 32; i += 8)
        tb[y + i][x] = W[(size_t)(k0 + y + i) * N + n0 + x];
    __syncthreads();
    #pragma unroll
    for (int i = 0; i < 32; i += 8)
        WT[(size_t)(n0 + y + i) * K + k0 + x] = tf32_f(tb[x][y + i]);
}
__global__ void k_wtrans_l(const float* __restrict__ W, float* __restrict__ WT) {
    __shared__ float tb[32][33];
    int l = blockIdx.z;
    int k0 = blockIdx.x * 32, n0 = blockIdx.y * 32;
    int x = threadIdx.x, y = threadIdx.y;
    const float* Wl = W + (size_t)l * NH * NH;
    float* WTl = WT + (size_t)l * NH * NH;
    #pragma unroll
    for (int i = 0; i < 32; i += 8)
        tb[y + i][x] = Wl[(size_t)(k0 + y + i) * NH + n0 + x];
    __syncthreads();
    #pragma unroll
    for (int i = 0; i < 32; i += 8)
        WTl[(size_t)(n0 + y + i) * NH + k0 + x] = tf32_f(tb[x][y + i]);
}

// ---------------- SpMM (bf16 gather) + residual; output pre-rounded to tf32 ----------------
__device__ __forceinline__ void bf2_fma(uint32_t w, float v, float& a0, float& a1) {
    a0 += v * __uint_as_float(w << 16);
    a1 += v * __uint_as_float(w & 0xFFFF0000u);
}
__device__ __forceinline__ void acc_edge(uint4 x, float v, float* acc) {
    bf2_fma(x.x, v, acc[0], acc[1]); bf2_fma(x.y, v, acc[2], acc[3]);
    bf2_fma(x.z, v, acc[4], acc[5]); bf2_fma(x.w, v, acc[6], acc[7]);
}

__global__ void __launch_bounds__(128)
k_spmm_combine(const __nv_bfloat16* __restrict__ hb, const float* __restrict__ h0,
               float* __restrict__ out) {
    int row  = blockIdx.x * 4 + (threadIdx.x >> 5);
    int lane = threadIdx.x & 31;
    const uint4* __restrict__ hb4 = (const uint4*)hb;

    int beg = g_rowptr[row], end = g_rowptr[row + 1];
    float acc[8] = {0.f, 0.f, 0.f, 0.f, 0.f, 0.f, 0.f, 0.f};

    int e = beg;
    for (; e + 8 <= end; e += 8) {
        int2 E0 = g_edge[e],     E1 = g_edge[e + 1];
        int2 E2 = g_edge[e + 2], E3 = g_edge[e + 3];
        int2 E4 = g_edge[e + 4], E5 = g_edge[e + 5];
        int2 E6 = g_edge[e + 6], E7 = g_edge[e + 7];
        uint4 x0 = hb4[E0.x * 32 + lane];
        uint4 x1 = hb4[E1.x * 32 + lane];
        uint4 x2 = hb4[E2.x * 32 + lane];
        uint4 x3 = hb4[E3.x * 32 + lane];
        uint4 x4 = hb4[E4.x * 32 + lane];
        uint4 x5 = hb4[E5.x * 32 + lane];
        uint4 x6 = hb4[E6.x * 32 + lane];
        uint4 x7 = hb4[E7.x * 32 + lane];
        acc_edge(x0, __int_as_float(E0.y), acc);
        acc_edge(x1, __int_as_float(E1.y), acc);
        acc_edge(x2, __int_as_float(E2.y), acc);
        acc_edge(x3, __int_as_float(E3.y), acc);
        acc_edge(x4, __int_as_float(E4.y), acc);
        acc_edge(x5, __int_as_float(E5.y), acc);
        acc_edge(x6, __int_as_float(E6.y), acc);
        acc_edge(x7, __int_as_float(E7.y), acc);
    }
    for (; e < end; ++e) {
        int2 E = g_edge[e];
        uint4 x = hb4[E.x * 32 + lane];
        acc_edge(x, __int_as_float(E.y), acc);
    }

    const float4* __restrict__ h04 = (const float4*)h0;
    float4* __restrict__ o4 = (float4*)out;
    float4 z0 = h04[(size_t)row * 64 + lane * 2];
    float4 z1 = h04[(size_t)row * 64 + lane * 2 + 1];
    float4 oA, oB;
    oA.x = tf32_f((1.f - ALPHA) * acc[0] + ALPHA * z0.x);
    oA.y = tf32_f((1.f - ALPHA) * acc[1] + ALPHA * z0.y);
    oA.z = tf32_f((1.f - ALPHA) * acc[2] + ALPHA * z0.z);
    oA.w = tf32_f((1.f - ALPHA) * acc[3] + ALPHA * z0.w);
    oB.x = tf32_f((1.f - ALPHA) * acc[4] + ALPHA * z1.x);
    oB.y = tf32_f((1.f - ALPHA) * acc[5] + ALPHA * z1.y);
    oB.z = tf32_f((1.f - ALPHA) * acc[6] + ALPHA * z1.z);
    oB.w = tf32_f((1.f - ALPHA) * acc[7] + ALPHA * z1.w);
    o4[(size_t)row * 64 + lane * 2]     = oA;
    o4[(size_t)row * 64 + lane * 2 + 1] = oB;
}

__device__ __forceinline__ void mma_tf32(float& c0, float& c1, float& c2, float& c3,
                                         uint32_t a0, uint32_t a1, uint32_t a2, uint32_t a3,
                                         uint32_t b0, uint32_t b1) {
    asm volatile(
        "mma.sync.aligned.m16n8k8.row.col.f32.tf32.tf32.f32 "
        "{%0,%1,%2,%3}, {%4,%5,%6,%7}, {%8,%9}, {%0,%1,%2,%3};"
        : "+f"(c0), "+f"(c1), "+f"(c2), "+f"(c3)
        : "r"(a0), "r"(a1), "r"(a2), "r"(a3), "r"(b0), "r"(b1));
}

// ---------------- tf32 GEMM, ldmatrix fragments, B pre-transposed [n][k] ----------------
// C = A[M,K] @ WT[256,K]^T ; block 128x128, 8 warps (2m x 4n), warp tile 64x32
// mode 0: o = relu(D + bias) -> C2 (fp32), Cb (bf16); docvt=1 (A not pre-rounded)
// mode 1: o = relu(th*D + (1-th)*R) -> Cf if non-null, Cb if non-null; docvt=0
#define ASTR 36
#define TILE_EL (128 * ASTR)
#define MG_SMEM (4 * TILE_EL * 4)

__global__ void __launch_bounds__(256, 2)
k_mgemm(const float* __restrict__ A, const float* __restrict__ WT,
        const float* __restrict__ bias, const float* __restrict__ R,
        float th, float* __restrict__ Cf, float* __restrict__ C2,
        __nv_bfloat16* __restrict__ Cb,
        int M, int K, int mode, int docvt) {
    extern __shared__ float sm[];
    float* smA = sm;                       // [2][128][ASTR]
    float* smB = sm + 2 * TILE_EL;         // [2][128][ASTR]
    uint32_t sA = smem_u32(smA);
    uint32_t sB = smem_u32(smB);

    int tid  = threadIdx.x;
    int wid  = tid >> 5, lane = tid & 31;
    int g    = lane >> 2, t = lane & 3;
    int wm   = wid & 1;
    int wn   = wid >> 1;
    int m0   = blockIdx.x * 128;
    int n0   = blockIdx.y * 128;
    int nc   = K >> 5;

    // ldmatrix per-lane source offsets (bytes, within a tile buffer)
    int lr = lane & 7, sel = lane >> 3;
    uint32_t a_base = (uint32_t)(((wm * 64 + lr + (sel & 1) * 8) * ASTR + (sel >> 1) * 4) * 4);
    uint32_t b_base = (uint32_t)(((wn * 32 + (sel >> 1) * 8 + lr) * ASTR + (sel & 1) * 4) * 4);

    // staging: 128 rows x 32 floats each operand; 2 threads/row x 64B
    int sr = tid >> 1, scol = (tid & 1) << 4;
    const float* Asrc = A  + (size_t)(m0 + sr) * K + scol;
    const float* Bsrc = WT + (size_t)(n0 + sr) * K + scol;
    int abytes = (m0 + sr < M) ? 16 : 0;
    uint32_t dA0 = sA + (sr * ASTR + scol) * 4;
    uint32_t dB0 = sB + (sr * ASTR + scol) * 4;

    {
        #pragma unroll
        for (int q = 0; q < 4; ++q) cp16(dA0 + q * 16, Asrc + q * 4, abytes);
        #pragma unroll
        for (int q = 0; q < 4; ++q) cp16(dB0 + q * 16, Bsrc + q * 4, 16);
        CP_COMMIT();
    }

    float c[4][4][4];
    #pragma unroll
    for (int i = 0; i < 4; ++i)
        #pragma unroll
        for (int j = 0; j < 4; ++j)
            #pragma unroll
            for (int q = 0; q < 4; ++q) c[i][j][q] = 0.f;

    for (int ch = 0; ch < nc; ++ch) {
        int buf = ch & 1;
        bool more = (ch + 1 < nc);
        if (more) {
            int k0 = (ch + 1) << 5;
            int bo = buf ^ 1;
            uint32_t dA = dA0 + bo * TILE_EL * 4;
            uint32_t dB = dB0 + bo * TILE_EL * 4;
            #pragma unroll
            for (int q = 0; q < 4; ++q) cp16(dA + q * 16, Asrc + k0 + q * 4, abytes);
            #pragma unroll
            for (int q = 0; q < 4; ++q) cp16(dB + q * 16, Bsrc + k0 + q * 4, 16);
            CP_COMMIT();
            CP_WAIT1();
        } else {
            CP_WAIT0();
        }
        __syncthreads();

        uint32_t ab = sA + buf * TILE_EL * 4 + a_base;
        uint32_t bb = sB + buf * TILE_EL * 4 + b_base;
        #pragma unroll
        for (int ks = 0; ks < 4; ++ks) {
            uint32_t koff = (uint32_t)(ks * 8 * 4);
            uint32_t af[4][4];
            #pragma unroll
            for (int mf = 0; mf < 4; ++mf)
                LDSM4(af[mf][0], af[mf][1], af[mf][2], af[mf][3],
                      ab + (uint32_t)(mf * 16 * ASTR * 4) + koff);
            uint32_t bf[4][2];
            #pragma unroll
            for (int p = 0; p < 2; ++p)
                LDSM4(bf[2 * p][0], bf[2 * p][1], bf[2 * p + 1][0], bf[2 * p + 1][1],
                      bb + (uint32_t)(p * 16 * ASTR * 4) + koff);
            if (docvt) {
                #pragma unroll
                for (int mf = 0; mf < 4; ++mf)
                    #pragma unroll
                    for (int q = 0; q < 4; ++q)
                        af[mf][q] = tf32_u(__uint_as_float(af[mf][q]));
            }
            #pragma unroll
            for (int mf = 0; mf < 4; ++mf)
                #pragma unroll
                for (int nf = 0; nf < 4; ++nf)
                    mma_tf32(c[mf][nf][0], c[mf][nf][1], c[mf][nf][2], c[mf][nf][3],
                             af[mf][0], af[mf][1], af[mf][2], af[mf][3],
                             bf[nf][0], bf[nf][1]);
        }
        __syncthreads();
    }

    float oth = 1.f - th;
    #pragma unroll
    for (int mf = 0; mf < 4; ++mf) {
        int r0 = m0 + wm * 64 + mf * 16 + g;
        #pragma unroll
        for (int nf = 0; nf < 4; ++nf) {
            int ncol = n0 + wn * 32 + nf * 8 + 2 * t;
            #pragma unroll
            for (int half = 0; half < 2; ++half) {
                int m = r0 + half * 8;
                if (m >= M) continue;
                float d0 = c[mf][nf][half * 2 + 0];
                float d1 = c[mf][nf][half * 2 + 1];
                if (mode == 0) {
                    float2 o = make_float2(fmaxf(d0 + bias[ncol], 0.f),
                                           fmaxf(d1 + bias[ncol + 1], 0.f));
                    *reinterpret_cast<float2*>(C2 + (size_t)m * NH + ncol) = o;
                    *reinterpret_cast<__nv_bfloat162*>(Cb + (size_t)m * NH + ncol) =
                        __float22bfloat162_rn(o);
                } else {
                    float2 r2 = *reinterpret_cast<const float2*>(R + (size_t)m * NH + ncol);
                    float2 o = make_float2(fmaxf(th * d0 + oth * r2.x, 0.f),
                                           fmaxf(th * d1 + oth * r2.y, 0.f));
                    if (Cf)
                        *reinterpret_cast<float2*>(Cf + (size_t)m * NH + ncol) = o;
                    if (Cb)
                        *reinterpret_cast<__nv_bfloat162*>(Cb + (size_t)m * NH + ncol) =
                            __float22bfloat162_rn(o);
                }
            }
        }
    }
}

// ---------------- narrow tf32 GEMM (output layer, N=40), scalar-LDS path ----------------
#define KC 32
#define NSTRIDE 136
#define NA_EL (128 * ASTR)
#define NB_EL (KC * NSTRIDE)
#define N_SMEM ((2 * NA_EL + 2 * NB_EL) * 4)

__global__ void __launch_bounds__(256, 2)
k_ngemm(const float* __restrict__ A, const float* __restrict__ B,
        const float* __restrict__ bias, float* __restrict__ C,
        int M, int K, int Nn) {
    extern __shared__ float sm[];
    float* smA = sm;
    float* smB = sm + 2 * NA_EL;
    uint32_t sA = smem_u32(smA);
    uint32_t sB = smem_u32(smB);

    int tid  = threadIdx.x;
    int wid  = tid >> 5, lane = tid & 31;
    int g    = lane >> 2, t = lane & 3;
    int wm   = wid & 1;
    int wn   = wid >> 1;
    int m0   = blockIdx.x * 128;
    int nc   = K / KC;

    int ar = tid >> 1, ac = (tid & 1) << 4;
    int br = tid >> 3, bc = (tid & 7) << 4;

    const float* Asrc = A + (size_t)(m0 + ar) * K + ac;
    int abytes = (m0 + ar < M) ? 16 : 0;

    {
        cp16(sA + (ar * ASTR + ac) * 4, Asrc, abytes);
        cp16(sA + (ar * ASTR + ac + 4) * 4, Asrc + 4, abytes);
        cp16(sA + (ar * ASTR + ac + 8) * 4, Asrc + 8, abytes);
        cp16(sA + (ar * ASTR + ac + 12) * 4, Asrc + 12, abytes);
        #pragma unroll
        for (int q = 0; q < 4; ++q) {
            int gn = bc + q * 4;
            int bbytes = (Nn - gn >= 4) ? 16 : ((Nn - gn > 0) ? (Nn - gn) * 4 : 0);
            cp16(sB + (br * NSTRIDE + bc + q * 4) * 4,
                 B + (size_t)br * Nn + ((bbytes > 0) ? gn : 0), bbytes);
        }
        CP_COMMIT();
    }

    float c[4][4][4];
    #pragma unroll
    for (int i = 0; i < 4; ++i)
        #pragma unroll
        for (int j = 0; j < 4; ++j)
            #pragma unroll
            for (int q = 0; q < 4; ++q) c[i][j][q] = 0.f;

    for (int ch = 0; ch < nc; ++ch) {
        int buf = ch & 1;
        bool more = (ch + 1 < nc);
        if (more) {
            int k0 = (ch + 1) * KC;
            int bo = (buf ^ 1);
            uint32_t dA = sA + (bo * NA_EL + ar * ASTR + ac) * 4;
            const float* src = Asrc + k0;
            cp16(dA,      src,      abytes);
            cp16(dA + 16, src + 4,  abytes);
            cp16(dA + 32, src + 8,  abytes);
            cp16(dA + 48, src + 12, abytes);
            #pragma unroll
            for (int q = 0; q < 4; ++q) {
                int gn = bc + q * 4;
                int bbytes = (Nn - gn >= 4) ? 16 : ((Nn - gn > 0) ? (Nn - gn) * 4 : 0);
                cp16(sB + (bo * NB_EL + br * NSTRIDE + bc + q * 4) * 4,
                     B + (size_t)(k0 + br) * Nn + ((bbytes > 0) ? gn : 0), bbytes);
            }
            CP_COMMIT();
            CP_WAIT1();
        } else {
            CP_WAIT0();
        }
        __syncthreads();

        const float* As = smA + buf * NA_EL;
        const float* Bs = smB + buf * NB_EL;
        #pragma unroll
        for (int ks = 0; ks < 4; ++ks) {
            int kk = ks * 8;
            uint32_t af[4][4];
            #pragma unroll
            for (int mf = 0; mf < 4; ++mf) {
                int r = wm * 64 + mf * 16 + g;
                af[mf][0] = tf32_u(As[(r    ) * ASTR + kk + t    ]);
                af[mf][1] = tf32_u(As[(r + 8) * ASTR + kk + t    ]);
                af[mf][2] = tf32_u(As[(r    ) * ASTR + kk + t + 4]);
                af[mf][3] = tf32_u(As[(r + 8) * ASTR + kk + t + 4]);
            }
            uint32_t bf[4][2];
            #pragma unroll
            for (int nf = 0; nf < 4; ++nf) {
                int ncol = wn * 32 + nf * 8 + g;
                bf[nf][0] = tf32_u(Bs[(kk + t    ) * NSTRIDE + ncol]);
                bf[nf][1] = tf32_u(Bs[(kk + t + 4) * NSTRIDE + ncol]);
            }
            #pragma unroll
            for (int mf = 0; mf < 4; ++mf)
                #pragma unroll
                for (int nf = 0; nf < 4; ++nf)
                    mma_tf32(c[mf][nf][0], c[mf][nf][1], c[mf][nf][2], c[mf][nf][3],
                             af[mf][0], af[mf][1], af[mf][2], af[mf][3],
                             bf[nf][0], bf[nf][1]);
        }
        __syncthreads();
    }

    #pragma unroll
    for (int mf = 0; mf < 4; ++mf) {
        int r0 = m0 + wm * 64 + mf * 16 + g;
        #pragma unroll
        for (int nf = 0; nf < 4; ++nf) {
            int ncol = wn * 32 + nf * 8 + 2 * t;
            #pragma unroll
            for (int half = 0; half < 2; ++half) {
                int m = r0 + half * 8;
                if (m >= M) continue;
                float d0 = c[mf][nf][half * 2 + 0];
                float d1 = c[mf][nf][half * 2 + 1];
                if (ncol < Nn)     C[(size_t)m * Nn + ncol]     = d0 + bias[ncol];
                if (ncol + 1 < Nn) C[(size_t)m * Nn + ncol + 1] = d1 + bias[ncol + 1];
            }
        }
    }
}

// ---------------- launch ----------------
extern "C" void kernel_launch(void* const* d_in, const int* in_sizes, int n_in,
                              void* d_out, int out_size) {
    const float* features = (const float*)d_in[0];
    const int*   erows    = (const int*)  d_in[1];
    const int*   ecols    = (const int*)  d_in[2];
    const float* evals    = (const float*)d_in[3];
    const float* W_in     = (const float*)d_in[4];
    const float* b_in     = (const float*)d_in[5];
    const float* convW    = (const float*)d_in[6];
    const float* W_out    = (const float*)d_in[7];
    const float* b_out    = (const float*)d_in[8];
    float* out = (float*)d_out;

    const int E = in_sizes[1];
    const int Mn = NNODES;

    float* d_h;   cudaGetSymbolAddress((void**)&d_h,   g_h);
    float* d_h0;  cudaGetSymbolAddress((void**)&d_h0,  g_h0);
    float* d_tmp; cudaGetSymbolAddress((void**)&d_tmp, g_tmp);
    float* d_wtf; cudaGetSymbolAddress((void**)&d_wtf, g_wtf);
    __nv_bfloat16* d_hb; cudaGetSymbolAddress((void**)&d_hb, g_hb);

    cudaFuncSetAttribute(k_mgemm, cudaFuncAttributeMaxDynamicSharedMemorySize, MG_SMEM);
    cudaFuncSetAttribute(k_ngemm, cudaFuncAttributeMaxDynamicSharedMemorySize, N_SMEM);

    float* d_wt_in = d_wtf;                              // [256][512]
    float* d_wt_l  = d_wtf + (size_t)NH * NFEAT;         // NL x [256][256]

    int mg = (Mn + 127) / 128;
    dim3 tblk(32, 8);
    int np1 = Mn + 1;
    int nscan_blocks = (np1 + 1023) / 1024;

    // launch order keeps the input GEMM at index 3 (ncu capture target)
    k_zero_counts<<<(np1 + 255) / 256, 256>>>(np1);                           // 0
    k_hist<<<(E + 255) / 256, 256>>>(erows, E);                               // 1
    k_wtrans<<<dim3(NFEAT / 32, NH / 32), tblk>>>(W_in, d_wt_in, NFEAT, NH);  // 2

    // input layer: h0 = relu(F @ W_in + b_in); hb = bf16(h0)
    k_mgemm<<<dim3(mg, 2), 256, MG_SMEM>>>(features, d_wt_in, b_in, nullptr, 0.f,
                                           nullptr, d_h0, d_hb, Mn, NFEAT, 0, 1);  // 3

    k_scan_block<<<nscan_blocks, 1024>>>(np1);                                // 4
    k_scan_partials<<<1, 1024>>>(nscan_blocks);                               // 5
    k_scan_add_cursor<<<nscan_blocks, 1024>>>(np1);                           // 6
    k_scatter<<<(E + 255) / 256, 256>>>(erows, ecols, evals, E);              // 7
    k_wtrans_l<<<dim3(NH / 32, NH / 32, NL), tblk>>>(convW, d_wt_l);          // 8

    // ---- GCNII layers ----
    for (int l = 0; l < NL; ++l) {
        float theta = logf(0.5f / (float)(l + 1) + 1.0f);
        k_spmm_combine<<<Mn / 4, 128>>>(d_hb, d_h0, d_tmp);
        bool last = (l + 1 == NL);
        k_mgemm<<<dim3(mg, 2), 256, MG_SMEM>>>(
            d_tmp, d_wt_l + (size_t)l * NH * NH, nullptr, d_tmp, theta,
            last ? d_h : nullptr, nullptr, last ? nullptr : d_hb, Mn, NH, 1, 0);
    }

    // ---- output layer ----
    k_ngemm<<<dim3(mg, 1), 256, N_SMEM>>>(d_h, W_out, b_out, out, Mn, NH, NC);
}

// round 16
// speedup vs baseline: 1.5790x; 1.0097x over previous
#include <cuda_runtime.h>
#include <cuda_bf16.h>
#include <math.h>
#include <stdint.h>

#define NNODES 100000
#define NEDGES 3200000
#define NFEAT  512
#define NH     256
#define NC     40
#define NL     8
#define ALPHA  0.1f

// ---------------- scratch (device globals; no allocation allowed) ----------------
__device__ __align__(16) float g_h  [(size_t)NNODES * NH];
__device__ __align__(16) float g_h0 [(size_t)NNODES * NH];
__device__ __align__(16) float g_tmp[(size_t)NNODES * NH];
__device__ __align__(16) __nv_bfloat16 g_hb[(size_t)NNODES * NH];
__device__ __align__(16) float g_wtf[(size_t)NH * NFEAT + (size_t)NL * NH * NH];
__device__ __align__(16) int2 g_edge[NEDGES];
__device__ int   g_rowptr[NNODES + 1];
__device__ int   g_cursor[NNODES];
__device__ int   g_partial[1024];

__device__ __forceinline__ uint32_t smem_u32(const void* p) {
    uint32_t a;
    asm("{ .reg .u64 t; cvta.to.shared.u64 t, %1; cvt.u32.u64 %0, t; }" : "=r"(a) : "l"(p));
    return a;
}
__device__ __forceinline__ uint32_t tf32_u(float x) {
    uint32_t u;
    asm("cvt.rna.tf32.f32 %0, %1;" : "=r"(u) : "f"(x));
    return u;
}
__device__ __forceinline__ float tf32_f(float x) { return __uint_as_float(tf32_u(x)); }

__device__ __forceinline__ void cp16(uint32_t dst, const void* src, int bytes) {
    asm volatile("cp.async.ca.shared.global [%0], [%1], 16, %2;"
                 :: "r"(dst), "l"(src), "r"(bytes) : "memory");
}
#define CP_COMMIT() asm volatile("cp.async.commit_group;" ::: "memory")
#define CP_WAIT1()  asm volatile("cp.async.wait_group 1;" ::: "memory")
#define CP_WAIT0()  asm volatile("cp.async.wait_group 0;" ::: "memory")

#define LDSM4(r0, r1, r2, r3, addr)                                              \
    asm volatile("ldmatrix.sync.aligned.m8n8.x4.shared.b16 {%0,%1,%2,%3}, [%4];" \
                 : "=r"(r0), "=r"(r1), "=r"(r2), "=r"(r3) : "r"(addr))

// ---------------- CSR construction ----------------
__global__ void k_zero_counts(int n) {
    for (int i = blockIdx.x * blockDim.x + threadIdx.x; i < n; i += gridDim.x * blockDim.x)
        g_rowptr[i] = 0;
}
__global__ void k_hist(const int* __restrict__ rows, int e) {
    for (int i = blockIdx.x * blockDim.x + threadIdx.x; i < e; i += gridDim.x * blockDim.x)
        atomicAdd(&g_rowptr[rows[i] + 1], 1);
}
__global__ void k_scan_block(int n) {
    __shared__ int s[1024];
    int i = blockIdx.x * 1024 + threadIdx.x;
    int v = (i < n) ? g_rowptr[i] : 0;
    s[threadIdx.x] = v;
    __syncthreads();
    #pragma unroll
    for (int off = 1; off < 1024; off <<= 1) {
        int t = (threadIdx.x >= off) ? s[threadIdx.x - off] : 0;
        __syncthreads();
        s[threadIdx.x] += t;
        __syncthreads();
    }
    if (i < n) g_rowptr[i] = s[threadIdx.x];
    if (threadIdx.x == 1023) g_partial[blockIdx.x] = s[1023];
}
__global__ void k_scan_partials(int nb) {
    __shared__ int s[1024];
    int v = (threadIdx.x < nb) ? g_partial[threadIdx.x] : 0;
    s[threadIdx.x] = v;
    __syncthreads();
    #pragma unroll
    for (int off = 1; off < 1024; off <<= 1) {
        int t = (threadIdx.x >= off) ? s[threadIdx.x - off] : 0;
        __syncthreads();
        s[threadIdx.x] += t;
        __syncthreads();
    }
    if (threadIdx.x < nb) g_partial[threadIdx.x] = s[threadIdx.x];
}
__global__ void k_scan_add_cursor(int n) {
    int i = blockIdx.x * 1024 + threadIdx.x;
    if (i < n) {
        int v = g_rowptr[i];
        if (blockIdx.x > 0) { v += g_partial[blockIdx.x - 1]; g_rowptr[i] = v; }
        if (i < n - 1) g_cursor[i] = v;
    }
}
__global__ void k_scatter(const int* __restrict__ rows, const int* __restrict__ cols,
                          const float* __restrict__ vals, int e) {
    for (int i = blockIdx.x * blockDim.x + threadIdx.x; i < e; i += gridDim.x * blockDim.x) {
        int r = rows[i];
        int p = atomicAdd(&g_cursor[r], 1);
        g_edge[p] = make_int2(cols[i], __float_as_int(vals[i]));
    }
}

// ---------------- weight transpose + tf32 round: WT[n][k] = rna(W[k][n]) ----------------
__global__ void k_wtrans(const float* __restrict__ W, float* __restrict__ WT,
                         int K, int N) {
    __shared__ float tb[32][33];
    int k0 = blockIdx.x * 32, n0 = blockIdx.y * 32;
    int x = threadIdx.x, y = threadIdx.y;   // 32 x 8
    #pragma unroll
    for (int i = 0; i < 32; i += 8)
        tb[y + i][x] = W[(size_t)(k0 + y + i) * N + n0 + x];
    __syncthreads();
    #pragma unroll
    for (int i = 0; i < 32; i += 8)
        WT[(size_t)(n0 + y + i) * K + k0 + x] = tf32_f(tb[x][y + i]);
}
__global__ void k_wtrans_l(const float* __restrict__ W, float* __restrict__ WT) {
    __shared__ float tb[32][33];
    int l = blockIdx.z;
    int k0 = blockIdx.x * 32, n0 = blockIdx.y * 32;
    int x = threadIdx.x, y = threadIdx.y;
    const float* Wl = W + (size_t)l * NH * NH;
    float* WTl = WT + (size_t)l * NH * NH;
    #pragma unroll
    for (int i = 0; i < 32; i += 8)
        tb[y + i][x] = Wl[(size_t)(k0 + y + i) * NH + n0 + x];
    __syncthreads();
    #pragma unroll
    for (int i = 0; i < 32; i += 8)
        WTl[(size_t)(n0 + y + i) * NH + k0 + x] = tf32_f(tb[x][y + i]);
}

// ---------------- SpMM (bf16 gather) + residual; output pre-rounded to tf32 ----------------
__device__ __forceinline__ void bf2_fma(uint32_t w, float v, float& a0, float& a1) {
    a0 += v * __uint_as_float(w << 16);
    a1 += v * __uint_as_float(w & 0xFFFF0000u);
}
__device__ __forceinline__ void acc_edge(uint4 x, float v, float* acc) {
    bf2_fma(x.x, v, acc[0], acc[1]); bf2_fma(x.y, v, acc[2], acc[3]);
    bf2_fma(x.z, v, acc[4], acc[5]); bf2_fma(x.w, v, acc[6], acc[7]);
}

__global__ void __launch_bounds__(128)
k_spmm_combine(const __nv_bfloat16* __restrict__ hb, const float* __restrict__ h0,
               float* __restrict__ out) {
    int row  = blockIdx.x * 4 + (threadIdx.x >> 5);
    int lane = threadIdx.x & 31;
    const uint4* __restrict__ hb4 = (const uint4*)hb;

    int beg = g_rowptr[row], end = g_rowptr[row + 1];
    float acc[8] = {0.f, 0.f, 0.f, 0.f, 0.f, 0.f, 0.f, 0.f};

    int e = beg;
    for (; e + 8 <= end; e += 8) {
        int2 E0 = g_edge[e],     E1 = g_edge[e + 1];
        int2 E2 = g_edge[e + 2], E3 = g_edge[e + 3];
        int2 E4 = g_edge[e + 4], E5 = g_edge[e + 5];
        int2 E6 = g_edge[e + 6], E7 = g_edge[e + 7];
        uint4 x0 = hb4[E0.x * 32 + lane];
        uint4 x1 = hb4[E1.x * 32 + lane];
        uint4 x2 = hb4[E2.x * 32 + lane];
        uint4 x3 = hb4[E3.x * 32 + lane];
        uint4 x4 = hb4[E4.x * 32 + lane];
        uint4 x5 = hb4[E5.x * 32 + lane];
        uint4 x6 = hb4[E6.x * 32 + lane];
        uint4 x7 = hb4[E7.x * 32 + lane];
        acc_edge(x0, __int_as_float(E0.y), acc);
        acc_edge(x1, __int_as_float(E1.y), acc);
        acc_edge(x2, __int_as_float(E2.y), acc);
        acc_edge(x3, __int_as_float(E3.y), acc);
        acc_edge(x4, __int_as_float(E4.y), acc);
        acc_edge(x5, __int_as_float(E5.y), acc);
        acc_edge(x6, __int_as_float(E6.y), acc);
        acc_edge(x7, __int_as_float(E7.y), acc);
    }
    for (; e < end; ++e) {
        int2 E = g_edge[e];
        uint4 x = hb4[E.x * 32 + lane];
        acc_edge(x, __int_as_float(E.y), acc);
    }

    const float4* __restrict__ h04 = (const float4*)h0;
    float4* __restrict__ o4 = (float4*)out;
    float4 z0 = h04[(size_t)row * 64 + lane * 2];
    float4 z1 = h04[(size_t)row * 64 + lane * 2 + 1];
    float4 oA, oB;
    oA.x = tf32_f((1.f - ALPHA) * acc[0] + ALPHA * z0.x);
    oA.y = tf32_f((1.f - ALPHA) * acc[1] + ALPHA * z0.y);
    oA.z = tf32_f((1.f - ALPHA) * acc[2] + ALPHA * z0.z);
    oA.w = tf32_f((1.f - ALPHA) * acc[3] + ALPHA * z0.w);
    oB.x = tf32_f((1.f - ALPHA) * acc[4] + ALPHA * z1.x);
    oB.y = tf32_f((1.f - ALPHA) * acc[5] + ALPHA * z1.y);
    oB.z = tf32_f((1.f - ALPHA) * acc[6] + ALPHA * z1.z);
    oB.w = tf32_f((1.f - ALPHA) * acc[7] + ALPHA * z1.w);
    o4[(size_t)row * 64 + lane * 2]     = oA;
    o4[(size_t)row * 64 + lane * 2 + 1] = oB;
}

__device__ __forceinline__ void mma_tf32(float& c0, float& c1, float& c2, float& c3,
                                         uint32_t a0, uint32_t a1, uint32_t a2, uint32_t a3,
                                         uint32_t b0, uint32_t b1) {
    asm volatile(
        "mma.sync.aligned.m16n8k8.row.col.f32.tf32.tf32.f32 "
        "{%0,%1,%2,%3}, {%4,%5,%6,%7}, {%8,%9}, {%0,%1,%2,%3};"
        : "+f"(c0), "+f"(c1), "+f"(c2), "+f"(c3)
        : "r"(a0), "r"(a1), "r"(a2), "r"(a3), "r"(b0), "r"(b1));
}

// ---------------- tf32 GEMM, ldmatrix fragments, B pre-transposed [n][k] ----------------
// C = A[M,K] @ WT[256,K]^T ; block 128x128, 8 warps (2m x 4n), warp tile 64x32
// mode 0: o = relu(D + bias) -> C2 (fp32), Cb (bf16); docvt=1 (A not pre-rounded)
// mode 1: o = relu(th*D + (1-th)*R) -> Cf if non-null, Cb if non-null; docvt=0
#define ASTR 36
#define TILE_EL (128 * ASTR)
#define MG_SMEM (4 * TILE_EL * 4)

__global__ void __launch_bounds__(256, 2)
k_mgemm(const float* __restrict__ A, const float* __restrict__ WT,
        const float* __restrict__ bias, const float* __restrict__ R,
        float th, float* __restrict__ Cf, float* __restrict__ C2,
        __nv_bfloat16* __restrict__ Cb,
        int M, int K, int mode, int docvt) {
    extern __shared__ float sm[];
    float* smA = sm;                       // [2][128][ASTR]
    float* smB = sm + 2 * TILE_EL;         // [2][128][ASTR]
    uint32_t sA = smem_u32(smA);
    uint32_t sB = smem_u32(smB);

    int tid  = threadIdx.x;
    int wid  = tid >> 5, lane = tid & 31;
    int g    = lane >> 2, t = lane & 3;
    int wm   = wid & 1;
    int wn   = wid >> 1;
    int m0   = blockIdx.x * 128;
    int n0   = blockIdx.y * 128;
    int nc   = K >> 5;

    // ldmatrix per-lane source offsets (bytes, within a tile buffer)
    int lr = lane & 7, sel = lane >> 3;
    uint32_t a_base = (uint32_t)(((wm * 64 + lr + (sel & 1) * 8) * ASTR + (sel >> 1) * 4) * 4);
    uint32_t b_base = (uint32_t)(((wn * 32 + (sel >> 1) * 8 + lr) * ASTR + (sel & 1) * 4) * 4);

    // staging: 128 rows x 32 floats each operand; 2 threads/row x 64B
    int sr = tid >> 1, scol = (tid & 1) << 4;
    const float* Asrc = A  + (size_t)(m0 + sr) * K + scol;
    const float* Bsrc = WT + (size_t)(n0 + sr) * K + scol;
    int abytes = (m0 + sr < M) ? 16 : 0;
    uint32_t dA0 = sA + (sr * ASTR + scol) * 4;
    uint32_t dB0 = sB + (sr * ASTR + scol) * 4;

    {
        #pragma unroll
        for (int q = 0; q < 4; ++q) cp16(dA0 + q * 16, Asrc + q * 4, abytes);
        #pragma unroll
        for (int q = 0; q < 4; ++q) cp16(dB0 + q * 16, Bsrc + q * 4, 16);
        CP_COMMIT();
    }

    float c[4][4][4];
    #pragma unroll
    for (int i = 0; i < 4; ++i)
        #pragma unroll
        for (int j = 0; j < 4; ++j)
            #pragma unroll
            for (int q = 0; q < 4; ++q) c[i][j][q] = 0.f;

    for (int ch = 0; ch < nc; ++ch) {
        int buf = ch & 1;
        bool more = (ch + 1 < nc);
        if (more) {
            int k0 = (ch + 1) << 5;
            int bo = buf ^ 1;
            uint32_t dA = dA0 + bo * TILE_EL * 4;
            uint32_t dB = dB0 + bo * TILE_EL * 4;
            #pragma unroll
            for (int q = 0; q < 4; ++q) cp16(dA + q * 16, Asrc + k0 + q * 4, abytes);
            #pragma unroll
            for (int q = 0; q < 4; ++q) cp16(dB + q * 16, Bsrc + k0 + q * 4, 16);
            CP_COMMIT();
            CP_WAIT1();
        } else {
            CP_WAIT0();
        }
        __syncthreads();

        uint32_t ab = sA + buf * TILE_EL * 4 + a_base;
        uint32_t bb = sB + buf * TILE_EL * 4 + b_base;
        #pragma unroll
        for (int ks = 0; ks < 4; ++ks) {
            uint32_t koff = (uint32_t)(ks * 8 * 4);
            uint32_t af[4][4];
            #pragma unroll
            for (int mf = 0; mf < 4; ++mf)
                LDSM4(af[mf][0], af[mf][1], af[mf][2], af[mf][3],
                      ab + (uint32_t)(mf * 16 * ASTR * 4) + koff);
            uint32_t bf[4][2];
            #pragma unroll
            for (int p = 0; p < 2; ++p)
                LDSM4(bf[2 * p][0], bf[2 * p][1], bf[2 * p + 1][0], bf[2 * p + 1][1],
                      bb + (uint32_t)(p * 16 * ASTR * 4) + koff);
            if (docvt) {
                #pragma unroll
                for (int mf = 0; mf < 4; ++mf)
                    #pragma unroll
                    for (int q = 0; q < 4; ++q)
                        af[mf][q] = tf32_u(__uint_as_float(af[mf][q]));
            }
            #pragma unroll
            for (int mf = 0; mf < 4; ++mf)
                #pragma unroll
                for (int nf = 0; nf < 4; ++nf)
                    mma_tf32(c[mf][nf][0], c[mf][nf][1], c[mf][nf][2], c[mf][nf][3],
                             af[mf][0], af[mf][1], af[mf][2], af[mf][3],
                             bf[nf][0], bf[nf][1]);
        }
        __syncthreads();
    }

    float oth = 1.f - th;
    #pragma unroll
    for (int mf = 0; mf < 4; ++mf) {
        int r0 = m0 + wm * 64 + mf * 16 + g;
        #pragma unroll
        for (int nf = 0; nf < 4; ++nf) {
            int ncol = n0 + wn * 32 + nf * 8 + 2 * t;
            #pragma unroll
            for (int half = 0; half < 2; ++half) {
                int m = r0 + half * 8;
                if (m >= M) continue;
                float d0 = c[mf][nf][half * 2 + 0];
                float d1 = c[mf][nf][half * 2 + 1];
                if (mode == 0) {
                    float2 o = make_float2(fmaxf(d0 + bias[ncol], 0.f),
                                           fmaxf(d1 + bias[ncol + 1], 0.f));
                    *reinterpret_cast<float2*>(C2 + (size_t)m * NH + ncol) = o;
                    *reinterpret_cast<__nv_bfloat162*>(Cb + (size_t)m * NH + ncol) =
                        __float22bfloat162_rn(o);
                } else {
                    float2 r2 = *reinterpret_cast<const float2*>(R + (size_t)m * NH + ncol);
                    float2 o = make_float2(fmaxf(th * d0 + oth * r2.x, 0.f),
                                           fmaxf(th * d1 + oth * r2.y, 0.f));
                    if (Cf)
                        *reinterpret_cast<float2*>(Cf + (size_t)m * NH + ncol) = o;
                    if (Cb)
                        *reinterpret_cast<__nv_bfloat162*>(Cb + (size_t)m * NH + ncol) =
                            __float22bfloat162_rn(o);
                }
            }
        }
    }
}

// ---------------- narrow tf32 GEMM (output layer, N=40), scalar-LDS path ----------------
#define KC 32
#define NSTRIDE 136
#define NA_EL (128 * ASTR)
#define NB_EL (KC * NSTRIDE)
#define N_SMEM ((2 * NA_EL + 2 * NB_EL) * 4)

__global__ void __launch_bounds__(256, 2)
k_ngemm(const float* __restrict__ A, const float* __restrict__ B,
        const float* __restrict__ bias, float* __restrict__ C,
        int M, int K, int Nn) {
    extern __shared__ float sm[];
    float* smA = sm;
    float* smB = sm + 2 * NA_EL;
    uint32_t sA = smem_u32(smA);
    uint32_t sB = smem_u32(smB);

    int tid  = threadIdx.x;
    int wid  = tid >> 5, lane = tid & 31;
    int g    = lane >> 2, t = lane & 3;
    int wm   = wid & 1;
    int wn   = wid >> 1;
    int m0   = blockIdx.x * 128;
    int nc   = K / KC;

    int ar = tid >> 1, ac = (tid & 1) << 4;
    int br = tid >> 3, bc = (tid & 7) << 4;

    const float* Asrc = A + (size_t)(m0 + ar) * K + ac;
    int abytes = (m0 + ar < M) ? 16 : 0;

    {
        cp16(sA + (ar * ASTR + ac) * 4, Asrc, abytes);
        cp16(sA + (ar * ASTR + ac + 4) * 4, Asrc + 4, abytes);
        cp16(sA + (ar * ASTR + ac + 8) * 4, Asrc + 8, abytes);
        cp16(sA + (ar * ASTR + ac + 12) * 4, Asrc + 12, abytes);
        #pragma unroll
        for (int q = 0; q < 4; ++q) {
            int gn = bc + q * 4;
            int bbytes = (Nn - gn >= 4) ? 16 : ((Nn - gn > 0) ? (Nn - gn) * 4 : 0);
            cp16(sB + (br * NSTRIDE + bc + q * 4) * 4,
                 B + (size_t)br * Nn + ((bbytes > 0) ? gn : 0), bbytes);
        }
        CP_COMMIT();
    }

    float c[4][4][4];
    #pragma unroll
    for (int i = 0; i < 4; ++i)
        #pragma unroll
        for (int j = 0; j < 4; ++j)
            #pragma unroll
            for (int q = 0; q < 4; ++q) c[i][j][q] = 0.f;

    for (int ch = 0; ch < nc; ++ch) {
        int buf = ch & 1;
        bool more = (ch + 1 < nc);
        if (more) {
            int k0 = (ch + 1) * KC;
            int bo = (buf ^ 1);
            uint32_t dA = sA + (bo * NA_EL + ar * ASTR + ac) * 4;
            const float* src = Asrc + k0;
            cp16(dA,      src,      abytes);
            cp16(dA + 16, src + 4,  abytes);
            cp16(dA + 32, src + 8,  abytes);
            cp16(dA + 48, src + 12, abytes);
            #pragma unroll
            for (int q = 0; q < 4; ++q) {
                int gn = bc + q * 4;
                int bbytes = (Nn - gn >= 4) ? 16 : ((Nn - gn > 0) ? (Nn - gn) * 4 : 0);
                cp16(sB + (bo * NB_EL + br * NSTRIDE + bc + q * 4) * 4,
                     B + (size_t)(k0 + br) * Nn + ((bbytes > 0) ? gn : 0), bbytes);
            }
            CP_COMMIT();
            CP_WAIT1();
        } else {
            CP_WAIT0();
        }
        __syncthreads();

        const float* As = smA + buf * NA_EL;
        const float* Bs = smB + buf * NB_EL;
        #pragma unroll
        for (int ks = 0; ks < 4; ++ks) {
            int kk = ks * 8;
            uint32_t af[4][4];
            #pragma unroll
            for (int mf = 0; mf < 4; ++mf) {
                int r = wm * 64 + mf * 16 + g;
                af[mf][0] = tf32_u(As[(r    ) * ASTR + kk + t    ]);
                af[mf][1] = tf32_u(As[(r + 8) * ASTR + kk + t    ]);
                af[mf][2] = tf32_u(As[(r    ) * ASTR + kk + t + 4]);
                af[mf][3] = tf32_u(As[(r + 8) * ASTR + kk + t + 4]);
            }
            uint32_t bf[4][2];
            #pragma unroll
            for (int nf = 0; nf < 4; ++nf) {
                int ncol = wn * 32 + nf * 8 + g;
                bf[nf][0] = tf32_u(Bs[(kk + t    ) * NSTRIDE + ncol]);
                bf[nf][1] = tf32_u(Bs[(kk + t + 4) * NSTRIDE + ncol]);
            }
            #pragma unroll
            for (int mf = 0; mf < 4; ++mf)
                #pragma unroll
                for (int nf = 0; nf < 4; ++nf)
                    mma_tf32(c[mf][nf][0], c[mf][nf][1], c[mf][nf][2], c[mf][nf][3],
                             af[mf][0], af[mf][1], af[mf][2], af[mf][3],
                             bf[nf][0], bf[nf][1]);
        }
        __syncthreads();
    }

    #pragma unroll
    for (int mf = 0; mf < 4; ++mf) {
        int r0 = m0 + wm * 64 + mf * 16 + g;
        #pragma unroll
        for (int nf = 0; nf < 4; ++nf) {
            int ncol = wn * 32 + nf * 8 + 2 * t;
            #pragma unroll
            for (int half = 0; half < 2; ++half) {
                int m = r0 + half * 8;
                if (m >= M) continue;
                float d0 = c[mf][nf][half * 2 + 0];
                float d1 = c[mf][nf][half * 2 + 1];
                if (ncol < Nn)     C[(size_t)m * Nn + ncol]     = d0 + bias[ncol];
                if (ncol + 1 < Nn) C[(size_t)m * Nn + ncol + 1] = d1 + bias[ncol + 1];
            }
        }
    }
}

// ---------------- launch ----------------
extern "C" void kernel_launch(void* const* d_in, const int* in_sizes, int n_in,
                              void* d_out, int out_size) {
    const float* features = (const float*)d_in[0];
    const int*   erows    = (const int*)  d_in[1];
    const int*   ecols    = (const int*)  d_in[2];
    const float* evals    = (const float*)d_in[3];
    const float* W_in     = (const float*)d_in[4];
    const float* b_in     = (const float*)d_in[5];
    const float* convW    = (const float*)d_in[6];
    const float* W_out    = (const float*)d_in[7];
    const float* b_out    = (const float*)d_in[8];
    float* out = (float*)d_out;

    const int E = in_sizes[1];
    const int Mn = NNODES;

    float* d_h;   cudaGetSymbolAddress((void**)&d_h,   g_h);
    float* d_h0;  cudaGetSymbolAddress((void**)&d_h0,  g_h0);
    float* d_tmp; cudaGetSymbolAddress((void**)&d_tmp, g_tmp);
    float* d_wtf; cudaGetSymbolAddress((void**)&d_wtf, g_wtf);
    __nv_bfloat16* d_hb; cudaGetSymbolAddress((void**)&d_hb, g_hb);

    cudaFuncSetAttribute(k_mgemm, cudaFuncAttributeMaxDynamicSharedMemorySize, MG_SMEM);
    cudaFuncSetAttribute(k_ngemm, cudaFuncAttributeMaxDynamicSharedMemorySize, N_SMEM);

    float* d_wt_in = d_wtf;                              // [256][512]
    float* d_wt_l  = d_wtf + (size_t)NH * NFEAT;         // NL x [256][256]

    int mg = (Mn + 127) / 128;
    dim3 tblk(32, 8);
    int np1 = Mn + 1;
    int nscan_blocks = (np1 + 1023) / 1024;

    // fork resources (created per call; intentionally never destroyed — a stream
    // being captured must not be destroyed mid-capture, and a handful of leaked
    // handles over the harness's few kernel_launch calls is benign)
    cudaStream_t s2;
    cudaStreamCreateWithFlags(&s2, cudaStreamNonBlocking);
    cudaEvent_t evFork, evJoin;
    cudaEventCreateWithFlags(&evFork, cudaEventDisableTiming);
    cudaEventCreateWithFlags(&evJoin, cudaEventDisableTiming);

    // ---- fork: CSR build + layer-weight prep on s2, input GEMM on main ----
    cudaEventRecord(evFork, 0);
    cudaStreamWaitEvent(s2, evFork, 0);

    // s2 branch (no dependency on the input GEMM)
    k_zero_counts<<<(np1 + 255) / 256, 256, 0, s2>>>(np1);
    k_hist<<<(E + 255) / 256, 256, 0, s2>>>(erows, E);
    k_scan_block<<<nscan_blocks, 1024, 0, s2>>>(np1);
    k_scan_partials<<<1, 1024, 0, s2>>>(nscan_blocks);
    k_scan_add_cursor<<<nscan_blocks, 1024, 0, s2>>>(np1);
    k_scatter<<<(E + 255) / 256, 256, 0, s2>>>(erows, ecols, evals, E);
    k_wtrans_l<<<dim3(NH / 32, NH / 32, NL), tblk, 0, s2>>>(convW, d_wt_l);
    cudaEventRecord(evJoin, s2);

    // main branch: input layer  h0 = relu(F @ W_in + b_in); hb = bf16(h0)
    k_wtrans<<<dim3(NFEAT / 32, NH / 32), tblk>>>(W_in, d_wt_in, NFEAT, NH);
    k_mgemm<<<dim3(mg, 2), 256, MG_SMEM>>>(features, d_wt_in, b_in, nullptr, 0.f,
                                           nullptr, d_h0, d_hb, Mn, NFEAT, 0, 1);

    // join: layers need both branches
    cudaStreamWaitEvent(0, evJoin, 0);

    // ---- GCNII layers ----
    for (int l = 0; l < NL; ++l) {
        float theta = logf(0.5f / (float)(l + 1) + 1.0f);
        k_spmm_combine<<<Mn / 4, 128>>>(d_hb, d_h0, d_tmp);
        bool last = (l + 1 == NL);
        k_mgemm<<<dim3(mg, 2), 256, MG_SMEM>>>(
            d_tmp, d_wt_l + (size_t)l * NH * NH, nullptr, d_tmp, theta,
            last ? d_h : nullptr, nullptr, last ? nullptr : d_hb, Mn, NH, 1, 0);
    }

    // ---- output layer ----
    k_ngemm<<<dim3(mg, 1), 256, N_SMEM>>>(d_h, W_out, b_out, out, Mn, NH, NC);
}

// round 17
// speedup vs baseline: 1.5829x; 1.0024x over previous
#include <cuda_runtime.h>
#include <cuda_bf16.h>
#include <math.h>
#include <stdint.h>

#define NNODES 100000
#define NEDGES 3200000
#define NFEAT  512
#define NH     256
#define NC     40
#define NL     8
#define ALPHA  0.1f

// ---------------- scratch (device globals; no allocation allowed) ----------------
__device__ __align__(16) float g_h  [(size_t)NNODES * NH];
__device__ __align__(16) float g_h0 [(size_t)NNODES * NH];
__device__ __align__(16) float g_tmp[(size_t)NNODES * NH];
__device__ __align__(16) __nv_bfloat16 g_hb[(size_t)NNODES * NH];
__device__ __align__(16) float g_wtf[(size_t)NH * NFEAT + (size_t)NL * NH * NH];
__device__ __align__(16) int2 g_edge[NEDGES];
__device__ int   g_rowptr[NNODES + 1];
__device__ int   g_cursor[NNODES];
__device__ int   g_partial[1024];

__device__ __forceinline__ uint32_t smem_u32(const void* p) {
    uint32_t a;
    asm("{ .reg .u64 t; cvta.to.shared.u64 t, %1; cvt.u32.u64 %0, t; }" : "=r"(a) : "l"(p));
    return a;
}
__device__ __forceinline__ uint32_t tf32_u(float x) {
    uint32_t u;
    asm("cvt.rna.tf32.f32 %0, %1;" : "=r"(u) : "f"(x));
    return u;
}
__device__ __forceinline__ float tf32_f(float x) { return __uint_as_float(tf32_u(x)); }

__device__ __forceinline__ void cp16(uint32_t dst, const void* src, int bytes) {
    asm volatile("cp.async.ca.shared.global [%0], [%1], 16, %2;"
                 :: "r"(dst), "l"(src), "r"(bytes) : "memory");
}
#define CP_COMMIT() asm volatile("cp.async.commit_group;" ::: "memory")
#define CP_WAIT1()  asm volatile("cp.async.wait_group 1;" ::: "memory")
#define CP_WAIT0()  asm volatile("cp.async.wait_group 0;" ::: "memory")

#define LDSM4(r0, r1, r2, r3, addr)                                              \
    asm volatile("ldmatrix.sync.aligned.m8n8.x4.shared.b16 {%0,%1,%2,%3}, [%4];" \
                 : "=r"(r0), "=r"(r1), "=r"(r2), "=r"(r3) : "r"(addr))

// ---------------- CSR construction ----------------
__global__ void k_zero_counts(int n) {
    for (int i = blockIdx.x * blockDim.x + threadIdx.x; i < n; i += gridDim.x * blockDim.x)
        g_rowptr[i] = 0;
}
__global__ void k_hist(const int* __restrict__ rows, int e) {
    for (int i = blockIdx.x * blockDim.x + threadIdx.x; i < e; i += gridDim.x * blockDim.x)
        atomicAdd(&g_rowptr[rows[i] + 1], 1);
}
__global__ void k_scan_block(int n) {
    __shared__ int s[1024];
    int i = blockIdx.x * 1024 + threadIdx.x;
    int v = (i < n) ? g_rowptr[i] : 0;
    s[threadIdx.x] = v;
    __syncthreads();
    #pragma unroll
    for (int off = 1; off < 1024; off <<= 1) {
        int t = (threadIdx.x >= off) ? s[threadIdx.x - off] : 0;
        __syncthreads();
        s[threadIdx.x] += t;
        __syncthreads();
    }
    if (i < n) g_rowptr[i] = s[threadIdx.x];
    if (threadIdx.x == 1023) g_partial[blockIdx.x] = s[1023];
}
__global__ void k_scan_partials(int nb) {
    __shared__ int s[1024];
    int v = (threadIdx.x < nb) ? g_partial[threadIdx.x] : 0;
    s[threadIdx.x] = v;
    __syncthreads();
    #pragma unroll
    for (int off = 1; off < 1024; off <<= 1) {
        int t = (threadIdx.x >= off) ? s[threadIdx.x - off] : 0;
        __syncthreads();
        s[threadIdx.x] += t;
        __syncthreads();
    }
    if (threadIdx.x < nb) g_partial[threadIdx.x] = s[threadIdx.x];
}
__global__ void k_scan_add_cursor(int n) {
    int i = blockIdx.x * 1024 + threadIdx.x;
    if (i < n) {
        int v = g_rowptr[i];
        if (blockIdx.x > 0) { v += g_partial[blockIdx.x - 1]; g_rowptr[i] = v; }
        if (i < n - 1) g_cursor[i] = v;
    }
}
__global__ void k_scatter(const int* __restrict__ rows, const int* __restrict__ cols,
                          const float* __restrict__ vals, int e) {
    for (int i = blockIdx.x * blockDim.x + threadIdx.x; i < e; i += gridDim.x * blockDim.x) {
        int r = rows[i];
        int p = atomicAdd(&g_cursor[r], 1);
        g_edge[p] = make_int2(cols[i], __float_as_int(vals[i]));
    }
}

// ---------------- weight transpose + tf32 round: WT[n][k] = rna(W[k][n]) ----------------
__global__ void k_wtrans(const float* __restrict__ W, float* __restrict__ WT,
                         int K, int N) {
    __shared__ float tb[32][33];
    int k0 = blockIdx.x * 32, n0 = blockIdx.y * 32;
    int x = threadIdx.x, y = threadIdx.y;   // 32 x 8
    #pragma unroll
    for (int i = 0; i < 32; i += 8)
        tb[y + i][x] = W[(size_t)(k0 + y + i) * N + n0 + x];
    __syncthreads();
    #pragma unroll
    for (int i = 0; i < 32; i += 8)
        WT[(size_t)(n0 + y + i) * K + k0 + x] = tf32_f(tb[x][y + i]);
}
__global__ void k_wtrans_l(const float* __restrict__ W, float* __restrict__ WT) {
    __shared__ float tb[32][33];
    int l = blockIdx.z;
    int k0 = blockIdx.x * 32, n0 = blockIdx.y * 32;
    int x = threadIdx.x, y = threadIdx.y;
    const float* Wl = W + (size_t)l * NH * NH;
    float* WTl = WT + (size_t)l * NH * NH;
    #pragma unroll
    for (int i = 0; i < 32; i += 8)
        tb[y + i][x] = Wl[(size_t)(k0 + y + i) * NH + n0 + x];
    __syncthreads();
    #pragma unroll
    for (int i = 0; i < 32; i += 8)
        WTl[(size_t)(n0 + y + i) * NH + k0 + x] = tf32_f(tb[x][y + i]);
}

// ---------------- SpMM (bf16 gather) + residual; output pre-rounded to tf32 ----------------
__device__ __forceinline__ void bf2_fma(uint32_t w, float v, float& a0, float& a1) {
    a0 += v * __uint_as_float(w << 16);
    a1 += v * __uint_as_float(w & 0xFFFF0000u);
}
__device__ __forceinline__ void acc_edge(uint4 x, float v, float* acc) {
    bf2_fma(x.x, v, acc[0], acc[1]); bf2_fma(x.y, v, acc[2], acc[3]);
    bf2_fma(x.z, v, acc[4], acc[5]); bf2_fma(x.w, v, acc[6], acc[7]);
}

__global__ void __launch_bounds__(128)
k_spmm_combine(const __nv_bfloat16* __restrict__ hb, const float* __restrict__ h0,
               float* __restrict__ out) {
    int row  = blockIdx.x * 4 + (threadIdx.x >> 5);
    int lane = threadIdx.x & 31;
    const uint4* __restrict__ hb4 = (const uint4*)hb;

    int beg = g_rowptr[row], end = g_rowptr[row + 1];
    float acc[8] = {0.f, 0.f, 0.f, 0.f, 0.f, 0.f, 0.f, 0.f};

    int e = beg;
    for (; e + 8 <= end; e += 8) {
        int2 E0 = g_edge[e],     E1 = g_edge[e + 1];
        int2 E2 = g_edge[e + 2], E3 = g_edge[e + 3];
        int2 E4 = g_edge[e + 4], E5 = g_edge[e + 5];
        int2 E6 = g_edge[e + 6], E7 = g_edge[e + 7];
        uint4 x0 = hb4[E0.x * 32 + lane];
        uint4 x1 = hb4[E1.x * 32 + lane];
        uint4 x2 = hb4[E2.x * 32 + lane];
        uint4 x3 = hb4[E3.x * 32 + lane];
        uint4 x4 = hb4[E4.x * 32 + lane];
        uint4 x5 = hb4[E5.x * 32 + lane];
        uint4 x6 = hb4[E6.x * 32 + lane];
        uint4 x7 = hb4[E7.x * 32 + lane];
        acc_edge(x0, __int_as_float(E0.y), acc);
        acc_edge(x1, __int_as_float(E1.y), acc);
        acc_edge(x2, __int_as_float(E2.y), acc);
        acc_edge(x3, __int_as_float(E3.y), acc);
        acc_edge(x4, __int_as_float(E4.y), acc);
        acc_edge(x5, __int_as_float(E5.y), acc);
        acc_edge(x6, __int_as_float(E6.y), acc);
        acc_edge(x7, __int_as_float(E7.y), acc);
    }
    for (; e < end; ++e) {
        int2 E = g_edge[e];
        uint4 x = hb4[E.x * 32 + lane];
        acc_edge(x, __int_as_float(E.y), acc);
    }

    const float4* __restrict__ h04 = (const float4*)h0;
    float4* __restrict__ o4 = (float4*)out;
    float4 z0 = h04[(size_t)row * 64 + lane * 2];
    float4 z1 = h04[(size_t)row * 64 + lane * 2 + 1];
    float4 oA, oB;
    oA.x = tf32_f((1.f - ALPHA) * acc[0] + ALPHA * z0.x);
    oA.y = tf32_f((1.f - ALPHA) * acc[1] + ALPHA * z0.y);
    oA.z = tf32_f((1.f - ALPHA) * acc[2] + ALPHA * z0.z);
    oA.w = tf32_f((1.f - ALPHA) * acc[3] + ALPHA * z0.w);
    oB.x = tf32_f((1.f - ALPHA) * acc[4] + ALPHA * z1.x);
    oB.y = tf32_f((1.f - ALPHA) * acc[5] + ALPHA * z1.y);
    oB.z = tf32_f((1.f - ALPHA) * acc[6] + ALPHA * z1.z);
    oB.w = tf32_f((1.f - ALPHA) * acc[7] + ALPHA * z1.w);
    o4[(size_t)row * 64 + lane * 2]     = oA;
    o4[(size_t)row * 64 + lane * 2 + 1] = oB;
}

__device__ __forceinline__ void mma_tf32(float& c0, float& c1, float& c2, float& c3,
                                         uint32_t a0, uint32_t a1, uint32_t a2, uint32_t a3,
                                         uint32_t b0, uint32_t b1) {
    asm volatile(
        "mma.sync.aligned.m16n8k8.row.col.f32.tf32.tf32.f32 "
        "{%0,%1,%2,%3}, {%4,%5,%6,%7}, {%8,%9}, {%0,%1,%2,%3};"
        : "+f"(c0), "+f"(c1), "+f"(c2), "+f"(c3)
        : "r"(a0), "r"(a1), "r"(a2), "r"(a3), "r"(b0), "r"(b1));
}

// ---------------- tf32 GEMM, ldmatrix fragments, B pre-transposed [n][k] ----------------
// C = A[M,K] @ WT[256,K]^T ; block 128x128, 8 warps (2m x 4n), warp tile 64x32
// grid = (n_blocks, m_blocks): n-blocks sharing an A row are launch-adjacent -> L2 A-reuse
// mode 0: o = relu(D + bias) -> C2 (fp32), Cb (bf16); docvt=1 (A not pre-rounded)
// mode 1: o = relu(th*D + (1-th)*R) -> Cf if non-null, Cb if non-null; docvt=0
#define ASTR 36
#define TILE_EL (128 * ASTR)
#define MG_SMEM (4 * TILE_EL * 4)

__global__ void __launch_bounds__(256, 2)
k_mgemm(const float* __restrict__ A, const float* __restrict__ WT,
        const float* __restrict__ bias, const float* __restrict__ R,
        float th, float* __restrict__ Cf, float* __restrict__ C2,
        __nv_bfloat16* __restrict__ Cb,
        int M, int K, int mode, int docvt) {
    extern __shared__ float sm[];
    float* smA = sm;                       // [2][128][ASTR]
    float* smB = sm + 2 * TILE_EL;         // [2][128][ASTR]
    uint32_t sA = smem_u32(smA);
    uint32_t sB = smem_u32(smB);

    int tid  = threadIdx.x;
    int wid  = tid >> 5, lane = tid & 31;
    int g    = lane >> 2, t = lane & 3;
    int wm   = wid & 1;
    int wn   = wid >> 1;
    int m0   = blockIdx.y * 128;           // m on the slow axis
    int n0   = blockIdx.x * 128;           // n on the fast axis (adjacent blocks share A)
    int nc   = K >> 5;

    // ldmatrix per-lane source offsets (bytes, within a tile buffer)
    int lr = lane & 7, sel = lane >> 3;
    uint32_t a_base = (uint32_t)(((wm * 64 + lr + (sel & 1) * 8) * ASTR + (sel >> 1) * 4) * 4);
    uint32_t b_base = (uint32_t)(((wn * 32 + (sel >> 1) * 8 + lr) * ASTR + (sel & 1) * 4) * 4);

    // staging: 128 rows x 32 floats each operand; 2 threads/row x 64B
    int sr = tid >> 1, scol = (tid & 1) << 4;
    const float* Asrc = A  + (size_t)(m0 + sr) * K + scol;
    const float* Bsrc = WT + (size_t)(n0 + sr) * K + scol;
    int abytes = (m0 + sr < M) ? 16 : 0;
    uint32_t dA0 = sA + (sr * ASTR + scol) * 4;
    uint32_t dB0 = sB + (sr * ASTR + scol) * 4;

    {
        #pragma unroll
        for (int q = 0; q < 4; ++q) cp16(dA0 + q * 16, Asrc + q * 4, abytes);
        #pragma unroll
        for (int q = 0; q < 4; ++q) cp16(dB0 + q * 16, Bsrc + q * 4, 16);
        CP_COMMIT();
    }

    float c[4][4][4];
    #pragma unroll
    for (int i = 0; i < 4; ++i)
        #pragma unroll
        for (int j = 0; j < 4; ++j)
            #pragma unroll
            for (int q = 0; q < 4; ++q) c[i][j][q] = 0.f;

    for (int ch = 0; ch < nc; ++ch) {
        int buf = ch & 1;
        bool more = (ch + 1 < nc);
        if (more) {
            int k0 = (ch + 1) << 5;
            int bo = buf ^ 1;
            uint32_t dA = dA0 + bo * TILE_EL * 4;
            uint32_t dB = dB0 + bo * TILE_EL * 4;
            #pragma unroll
            for (int q = 0; q < 4; ++q) cp16(dA + q * 16, Asrc + k0 + q * 4, abytes);
            #pragma unroll
            for (int q = 0; q < 4; ++q) cp16(dB + q * 16, Bsrc + k0 + q * 4, 16);
            CP_COMMIT();
            CP_WAIT1();
        } else {
            CP_WAIT0();
        }
        __syncthreads();

        uint32_t ab = sA + buf * TILE_EL * 4 + a_base;
        uint32_t bb = sB + buf * TILE_EL * 4 + b_base;
        #pragma unroll
        for (int ks = 0; ks < 4; ++ks) {
            uint32_t koff = (uint32_t)(ks * 8 * 4);
            uint32_t af[4][4];
            #pragma unroll
            for (int mf = 0; mf < 4; ++mf)
                LDSM4(af[mf][0], af[mf][1], af[mf][2], af[mf][3],
                      ab + (uint32_t)(mf * 16 * ASTR * 4) + koff);
            uint32_t bf[4][2];
            #pragma unroll
            for (int p = 0; p < 2; ++p)
                LDSM4(bf[2 * p][0], bf[2 * p][1], bf[2 * p + 1][0], bf[2 * p + 1][1],
                      bb + (uint32_t)(p * 16 * ASTR * 4) + koff);
            if (docvt) {
                #pragma unroll
                for (int mf = 0; mf < 4; ++mf)
                    #pragma unroll
                    for (int q = 0; q < 4; ++q)
                        af[mf][q] = tf32_u(__uint_as_float(af[mf][q]));
            }
            #pragma unroll
            for (int mf = 0; mf < 4; ++mf)
                #pragma unroll
                for (int nf = 0; nf < 4; ++nf)
                    mma_tf32(c[mf][nf][0], c[mf][nf][1], c[mf][nf][2], c[mf][nf][3],
                             af[mf][0], af[mf][1], af[mf][2], af[mf][3],
                             bf[nf][0], bf[nf][1]);
        }
        __syncthreads();
    }

    float oth = 1.f - th;
    #pragma unroll
    for (int mf = 0; mf < 4; ++mf) {
        int r0 = m0 + wm * 64 + mf * 16 + g;
        #pragma unroll
        for (int nf = 0; nf < 4; ++nf) {
            int ncol = n0 + wn * 32 + nf * 8 + 2 * t;
            #pragma unroll
            for (int half = 0; half < 2; ++half) {
                int m = r0 + half * 8;
                if (m >= M) continue;
                float d0 = c[mf][nf][half * 2 + 0];
                float d1 = c[mf][nf][half * 2 + 1];
                if (mode == 0) {
                    float2 o = make_float2(fmaxf(d0 + bias[ncol], 0.f),
                                           fmaxf(d1 + bias[ncol + 1], 0.f));
                    *reinterpret_cast<float2*>(C2 + (size_t)m * NH + ncol) = o;
                    *reinterpret_cast<__nv_bfloat162*>(Cb + (size_t)m * NH + ncol) =
                        __float22bfloat162_rn(o);
                } else {
                    float2 r2 = *reinterpret_cast<const float2*>(R + (size_t)m * NH + ncol);
                    float2 o = make_float2(fmaxf(th * d0 + oth * r2.x, 0.f),
                                           fmaxf(th * d1 + oth * r2.y, 0.f));
                    if (Cf)
                        *reinterpret_cast<float2*>(Cf + (size_t)m * NH + ncol) = o;
                    if (Cb)
                        *reinterpret_cast<__nv_bfloat162*>(Cb + (size_t)m * NH + ncol) =
                            __float22bfloat162_rn(o);
                }
            }
        }
    }
}

// ---------------- narrow tf32 GEMM (output layer, N=40), scalar-LDS path ----------------
#define KC 32
#define NSTRIDE 136
#define NA_EL (128 * ASTR)
#define NB_EL (KC * NSTRIDE)
#define N_SMEM ((2 * NA_EL + 2 * NB_EL) * 4)

__global__ void __launch_bounds__(256, 2)
k_ngemm(const float* __restrict__ A, const float* __restrict__ B,
        const float* __restrict__ bias, float* __restrict__ C,
        int M, int K, int Nn) {
    extern __shared__ float sm[];
    float* smA = sm;
    float* smB = sm + 2 * NA_EL;
    uint32_t sA = smem_u32(smA);
    uint32_t sB = smem_u32(smB);

    int tid  = threadIdx.x;
    int wid  = tid >> 5, lane = tid & 31;
    int g    = lane >> 2, t = lane & 3;
    int wm   = wid & 1;
    int wn   = wid >> 1;
    int m0   = blockIdx.x * 128;
    int nc   = K / KC;

    int ar = tid >> 1, ac = (tid & 1) << 4;
    int br = tid >> 3, bc = (tid & 7) << 4;

    const float* Asrc = A + (size_t)(m0 + ar) * K + ac;
    int abytes = (m0 + ar < M) ? 16 : 0;

    {
        cp16(sA + (ar * ASTR + ac) * 4, Asrc, abytes);
        cp16(sA + (ar * ASTR + ac + 4) * 4, Asrc + 4, abytes);
        cp16(sA + (ar * ASTR + ac + 8) * 4, Asrc + 8, abytes);
        cp16(sA + (ar * ASTR + ac + 12) * 4, Asrc + 12, abytes);
        #pragma unroll
        for (int q = 0; q < 4; ++q) {
            int gn = bc + q * 4;
            int bbytes = (Nn - gn >= 4) ? 16 : ((Nn - gn > 0) ? (Nn - gn) * 4 : 0);
            cp16(sB + (br * NSTRIDE + bc + q * 4) * 4,
                 B + (size_t)br * Nn + ((bbytes > 0) ? gn : 0), bbytes);
        }
        CP_COMMIT();
    }

    float c[4][4][4];
    #pragma unroll
    for (int i = 0; i < 4; ++i)
        #pragma unroll
        for (int j = 0; j < 4; ++j)
            #pragma unroll
            for (int q = 0; q < 4; ++q) c[i][j][q] = 0.f;

    for (int ch = 0; ch < nc; ++ch) {
        int buf = ch & 1;
        bool more = (ch + 1 < nc);
        if (more) {
            int k0 = (ch + 1) * KC;
            int bo = (buf ^ 1);
            uint32_t dA = sA + (bo * NA_EL + ar * ASTR + ac) * 4;
            const float* src = Asrc + k0;
            cp16(dA,      src,      abytes);
            cp16(dA + 16, src + 4,  abytes);
            cp16(dA + 32, src + 8,  abytes);
            cp16(dA + 48, src + 12, abytes);
            #pragma unroll
            for (int q = 0; q < 4; ++q) {
                int gn = bc + q * 4;
                int bbytes = (Nn - gn >= 4) ? 16 : ((Nn - gn > 0) ? (Nn - gn) * 4 : 0);
                cp16(sB + (bo * NB_EL + br * NSTRIDE + bc + q * 4) * 4,
                     B + (size_t)(k0 + br) * Nn + ((bbytes > 0) ? gn : 0), bbytes);
            }
            CP_COMMIT();
            CP_WAIT1();
        } else {
            CP_WAIT0();
        }
        __syncthreads();

        const float* As = smA + buf * NA_EL;
        const float* Bs = smB + buf * NB_EL;
        #pragma unroll
        for (int ks = 0; ks < 4; ++ks) {
            int kk = ks * 8;
            uint32_t af[4][4];
            #pragma unroll
            for (int mf = 0; mf < 4; ++mf) {
                int r = wm * 64 + mf * 16 + g;
                af[mf][0] = tf32_u(As[(r    ) * ASTR + kk + t    ]);
                af[mf][1] = tf32_u(As[(r + 8) * ASTR + kk + t    ]);
                af[mf][2] = tf32_u(As[(r    ) * ASTR + kk + t + 4]);
                af[mf][3] = tf32_u(As[(r + 8) * ASTR + kk + t + 4]);
            }
            uint32_t bf[4][2];
            #pragma unroll
            for (int nf = 0; nf < 4; ++nf) {
                int ncol = wn * 32 + nf * 8 + g;
                bf[nf][0] = tf32_u(Bs[(kk + t    ) * NSTRIDE + ncol]);
                bf[nf][1] = tf32_u(Bs[(kk + t + 4) * NSTRIDE + ncol]);
            }
            #pragma unroll
            for (int mf = 0; mf < 4; ++mf)
                #pragma unroll
                for (int nf = 0; nf < 4; ++nf)
                    mma_tf32(c[mf][nf][0], c[mf][nf][1], c[mf][nf][2], c[mf][nf][3],
                             af[mf][0], af[mf][1], af[mf][2], af[mf][3],
                             bf[nf][0], bf[nf][1]);
        }
        __syncthreads();
    }

    #pragma unroll
    for (int mf = 0; mf < 4; ++mf) {
        int r0 = m0 + wm * 64 + mf * 16 + g;
        #pragma unroll
        for (int nf = 0; nf < 4; ++nf) {
            int ncol = wn * 32 + nf * 8 + 2 * t;
            #pragma unroll
            for (int half = 0; half < 2; ++half) {
                int m = r0 + half * 8;
                if (m >= M) continue;
                float d0 = c[mf][nf][half * 2 + 0];
                float d1 = c[mf][nf][half * 2 + 1];
                if (ncol < Nn)     C[(size_t)m * Nn + ncol]     = d0 + bias[ncol];
                if (ncol + 1 < Nn) C[(size_t)m * Nn + ncol + 1] = d1 + bias[ncol + 1];
            }
        }
    }
}

// ---------------- launch ----------------
extern "C" void kernel_launch(void* const* d_in, const int* in_sizes, int n_in,
                              void* d_out, int out_size) {
    const float* features = (const float*)d_in[0];
    const int*   erows    = (const int*)  d_in[1];
    const int*   ecols    = (const int*)  d_in[2];
    const float* evals    = (const float*)d_in[3];
    const float* W_in     = (const float*)d_in[4];
    const float* b_in     = (const float*)d_in[5];
    const float* convW    = (const float*)d_in[6];
    const float* W_out    = (const float*)d_in[7];
    const float* b_out    = (const float*)d_in[8];
    float* out = (float*)d_out;

    const int E = in_sizes[1];
    const int Mn = NNODES;

    float* d_h;   cudaGetSymbolAddress((void**)&d_h,   g_h);
    float* d_h0;  cudaGetSymbolAddress((void**)&d_h0,  g_h0);
    float* d_tmp; cudaGetSymbolAddress((void**)&d_tmp, g_tmp);
    float* d_wtf; cudaGetSymbolAddress((void**)&d_wtf, g_wtf);
    __nv_bfloat16* d_hb; cudaGetSymbolAddress((void**)&d_hb, g_hb);

    cudaFuncSetAttribute(k_mgemm, cudaFuncAttributeMaxDynamicSharedMemorySize, MG_SMEM);
    cudaFuncSetAttribute(k_ngemm, cudaFuncAttributeMaxDynamicSharedMemorySize, N_SMEM);

    float* d_wt_in = d_wtf;                              // [256][512]
    float* d_wt_l  = d_wtf + (size_t)NH * NFEAT;         // NL x [256][256]

    int mg = (Mn + 127) / 128;
    dim3 tblk(32, 8);
    int np1 = Mn + 1;
    int nscan_blocks = (np1 + 1023) / 1024;

    // fork resources (created per call; intentionally never destroyed — a stream
    // being captured must not be destroyed mid-capture, and a handful of leaked
    // handles over the harness's few kernel_launch calls is benign)
    cudaStream_t s2;
    cudaStreamCreateWithFlags(&s2, cudaStreamNonBlocking);
    cudaEvent_t evFork, evJoin;
    cudaEventCreateWithFlags(&evFork, cudaEventDisableTiming);
    cudaEventCreateWithFlags(&evJoin, cudaEventDisableTiming);

    // ---- fork: CSR build + layer-weight prep on s2, input GEMM on main ----
    cudaEventRecord(evFork, 0);
    cudaStreamWaitEvent(s2, evFork, 0);

    // s2 branch (no dependency on the input GEMM)
    k_zero_counts<<<(np1 + 255) / 256, 256, 0, s2>>>(np1);
    k_hist<<<(E + 255) / 256, 256, 0, s2>>>(erows, E);
    k_scan_block<<<nscan_blocks, 1024, 0, s2>>>(np1);
    k_scan_partials<<<1, 1024, 0, s2>>>(nscan_blocks);
    k_scan_add_cursor<<<nscan_blocks, 1024, 0, s2>>>(np1);
    k_scatter<<<(E + 255) / 256, 256, 0, s2>>>(erows, ecols, evals, E);
    k_wtrans_l<<<dim3(NH / 32, NH / 32, NL), tblk, 0, s2>>>(convW, d_wt_l);
    cudaEventRecord(evJoin, s2);

    // main branch: input layer  h0 = relu(F @ W_in + b_in); hb = bf16(h0)
    k_wtrans<<<dim3(NFEAT / 32, NH / 32), tblk>>>(W_in, d_wt_in, NFEAT, NH);
    k_mgemm<<<dim3(2, mg), 256, MG_SMEM>>>(features, d_wt_in, b_in, nullptr, 0.f,
                                           nullptr, d_h0, d_hb, Mn, NFEAT, 0, 1);

    // join: layers need both branches
    cudaStreamWaitEvent(0, evJoin, 0);

    // ---- GCNII layers ----
    for (int l = 0; l < NL; ++l) {
        float theta = logf(0.5f / (float)(l + 1) + 1.0f);
        k_spmm_combine<<<Mn / 4, 128>>>(d_hb, d_h0, d_tmp);
        bool last = (l + 1 == NL);
        k_mgemm<<<dim3(2, mg), 256, MG_SMEM>>>(
            d_tmp, d_wt_l + (size_t)l * NH * NH, nullptr, d_tmp, theta,
            last ? d_h : nullptr, nullptr, last ? nullptr : d_hb, Mn, NH, 1, 0);
    }

    // ---- output layer ----
    k_ngemm<<<dim3(mg, 1), 256, N_SMEM>>>(d_h, W_out, b_out, out, Mn, NH, NC);
}